// round 1
// baseline (speedup 1.0000x reference)
#include <cuda_runtime.h>

// ---------------------------------------------------------------------------
// BAtten: windowed attention with 9 depthwise-conv KV templates.
// Key identity: depthwise conv (same 3x3 per channel) commutes with channel
// projection ->  K_i = conv_i(Wk x),  V_i = conv_i(Wv x).
// Attention logits: L[q,i,key] = sum_ab w_i[ab] * S[q, key+ab],
//   S[q,p] = Q[q] . xk[p]  over the 7x7 padded patch (49 positions).
// Output: O[q] = (1/Z) * A'[q,:] @ xv_patch, where A' is the attn collapsed
//   back through the conv templates onto the 49 patch positions.
// ---------------------------------------------------------------------------

#define BATCH 4
#define CDIM  256
#define HH    120
#define WWID  120
#define SP    (HH*WWID)          // 14400 spatial positions per batch
#define NB    24                 // windows per side
#define NWIN  (BATCH*NB*NB)      // 2304
#define QSCALE 0.17677669529663688f   // 32^-0.5

#define NEGW  (-0.5f)
#define POSW  (4.0f/3.0f)
#define NORW  (-0.375f)
#define CNORW (4.0f)

// scratch (channel-last [b][pos][c])
__device__ float g_xk[BATCH*SP*CDIM];
__device__ float g_xv[BATCH*SP*CDIM];
__device__ float g_xq[BATCH*SP*CDIM];
__device__ float g_y [BATCH*SP*CDIM];

// ---------------------------------------------------------------------------
// Kernel 1: fused triple projection  xk/xv/xq[p][c] = sum_k W*[c][k] x[b][k][p]
// (xq pre-scaled by dh^-0.5). 64x64 tile, BK=16, 4x4 microtile per thread x3.
// ---------------------------------------------------------------------------
__global__ __launch_bounds__(256) void proj3_kernel(
    const float* __restrict__ x,
    const float* __restrict__ Wk,
    const float* __restrict__ Wv,
    const float* __restrict__ Wq)
{
    __shared__ float As[16][68];
    __shared__ float Bk[16][68];
    __shared__ float Bv[16][68];
    __shared__ float Bq[16][68];

    const int p0 = blockIdx.x * 64;
    const int c0 = blockIdx.y * 64;
    const int b  = blockIdx.z;
    const int t  = threadIdx.x;
    const int tx = t & 15;      // c quad
    const int ty = t >> 4;      // p quad
    const int lkk = t >> 4, lpq = t & 15;   // A-tile load
    const int lcc = t >> 2, lkq = t & 3;    // B-tile load

    float ak[4][4], av[4][4], aq[4][4];
#pragma unroll
    for (int i = 0; i < 4; i++)
#pragma unroll
        for (int j = 0; j < 4; j++) { ak[i][j] = 0.f; av[i][j] = 0.f; aq[i][j] = 0.f; }

    const float* xb = x + (size_t)b * CDIM * SP;

    for (int kt = 0; kt < CDIM; kt += 16) {
        float4 a4 = *(const float4*)&xb[(size_t)(kt + lkk) * SP + p0 + lpq * 4];
        *(float4*)&As[lkk][lpq * 4] = a4;

        float4 bk4 = *(const float4*)&Wk[(c0 + lcc) * CDIM + kt + lkq * 4];
        float4 bv4 = *(const float4*)&Wv[(c0 + lcc) * CDIM + kt + lkq * 4];
        float4 bq4 = *(const float4*)&Wq[(c0 + lcc) * CDIM + kt + lkq * 4];
        Bk[lkq*4+0][lcc] = bk4.x; Bk[lkq*4+1][lcc] = bk4.y;
        Bk[lkq*4+2][lcc] = bk4.z; Bk[lkq*4+3][lcc] = bk4.w;
        Bv[lkq*4+0][lcc] = bv4.x; Bv[lkq*4+1][lcc] = bv4.y;
        Bv[lkq*4+2][lcc] = bv4.z; Bv[lkq*4+3][lcc] = bv4.w;
        Bq[lkq*4+0][lcc] = bq4.x; Bq[lkq*4+1][lcc] = bq4.y;
        Bq[lkq*4+2][lcc] = bq4.z; Bq[lkq*4+3][lcc] = bq4.w;
        __syncthreads();

#pragma unroll
        for (int kk = 0; kk < 16; kk++) {
            float4 a  = *(const float4*)&As[kk][ty * 4];
            float4 b1 = *(const float4*)&Bk[kk][tx * 4];
            float4 b2 = *(const float4*)&Bv[kk][tx * 4];
            float4 b3 = *(const float4*)&Bq[kk][tx * 4];
            const float ar[4] = {a.x, a.y, a.z, a.w};
            const float k1[4] = {b1.x, b1.y, b1.z, b1.w};
            const float v1[4] = {b2.x, b2.y, b2.z, b2.w};
            const float q1[4] = {b3.x, b3.y, b3.z, b3.w};
#pragma unroll
            for (int i = 0; i < 4; i++)
#pragma unroll
                for (int j = 0; j < 4; j++) {
                    ak[i][j] += ar[i] * k1[j];
                    av[i][j] += ar[i] * v1[j];
                    aq[i][j] += ar[i] * q1[j];
                }
        }
        __syncthreads();
    }

#pragma unroll
    for (int i = 0; i < 4; i++) {
        const int p = p0 + ty * 4 + i;
        const size_t base = ((size_t)b * SP + p) * CDIM + c0 + tx * 4;
        *(float4*)&g_xk[base] = make_float4(ak[i][0], ak[i][1], ak[i][2], ak[i][3]);
        *(float4*)&g_xv[base] = make_float4(av[i][0], av[i][1], av[i][2], av[i][3]);
        *(float4*)&g_xq[base] = make_float4(aq[i][0]*QSCALE, aq[i][1]*QSCALE,
                                            aq[i][2]*QSCALE, aq[i][3]*QSCALE);
    }
}

// ---------------------------------------------------------------------------
// Kernel 2: windowed attention. One CTA per window; thread t<200 = (head,q).
// ---------------------------------------------------------------------------
#define QROW 260                      // padded channel stride in smem
#define SQ_OFF 0
#define SK_OFF (25*QROW)
#define SV_OFF (SK_OFF + 49*QROW)
#define SA_OFF (SV_OFF + 49*QROW)
#define ATT_SMEM_BYTES ((SA_OFF + 200*49) * 4)

extern __shared__ float s_att[];

__global__ __launch_bounds__(256, 1) void attn_kernel()
{
    const int blk  = blockIdx.x;
    const int b    = blk / (NB * NB);
    const int wrem = blk % (NB * NB);
    const int wy = wrem / NB, wx = wrem % NB;
    const int t = threadIdx.x;

    // ---- load Q window (5x5) ----
    {
        const int gy0 = wy * 5, gx0 = wx * 5;
        for (int idx = t; idx < 25 * 64; idx += 256) {
            const int r  = idx >> 6;
            const int c4 = (idx & 63) << 2;
            const int y  = gy0 + r / 5;
            const int xx = gx0 + r % 5;
            const float4 v = *(const float4*)&g_xq[((size_t)b * SP + y * WWID + xx) * CDIM + c4];
            *(float4*)&s_att[SQ_OFF + r * QROW + c4] = v;
        }
    }
    // ---- load K/V padded patch (7x7, zero outside image) ----
    {
        const int ky0 = wy * 5 - 1, kx0 = wx * 5 - 1;
        for (int idx = t; idx < 49 * 64; idx += 256) {
            const int r  = idx >> 6;
            const int c4 = (idx & 63) << 2;
            const int y  = ky0 + r / 7;
            const int xx = kx0 + r % 7;
            float4 vk = make_float4(0.f, 0.f, 0.f, 0.f);
            float4 vv = make_float4(0.f, 0.f, 0.f, 0.f);
            if (y >= 0 && y < HH && xx >= 0 && xx < WWID) {
                const size_t g = ((size_t)b * SP + y * WWID + xx) * CDIM + c4;
                vk = *(const float4*)&g_xk[g];
                vv = *(const float4*)&g_xv[g];
            }
            *(float4*)&s_att[SK_OFF + r * QROW + c4] = vk;
            *(float4*)&s_att[SV_OFF + r * QROW + c4] = vv;
        }
    }
    __syncthreads();

    if (t < 200) {
        const int head = t / 25, q = t % 25;
        const int cb = head * 32;

        // Q vector in registers
        float qv[32];
#pragma unroll
        for (int c4 = 0; c4 < 8; c4++) {
            float4 v = *(const float4*)&s_att[SQ_OFF + q * QROW + cb + c4 * 4];
            qv[c4*4+0] = v.x; qv[c4*4+1] = v.y; qv[c4*4+2] = v.z; qv[c4*4+3] = v.w;
        }

        // S[p] = Q . xk(patch p)
        float S[49];
#pragma unroll
        for (int p = 0; p < 49; p++) {
            float acc = 0.f;
#pragma unroll
            for (int c4 = 0; c4 < 8; c4++) {
                float4 kv = *(const float4*)&s_att[SK_OFF + p * QROW + cb + c4 * 4];
                acc += qv[c4*4+0]*kv.x + qv[c4*4+1]*kv.y + qv[c4*4+2]*kv.z + qv[c4*4+3]*kv.w;
            }
            S[p] = acc;
        }

        // safe softmax shift: every template has sum(pos)=4, sum(|neg|)=3
        float mpos = S[0], mneg = S[0];
#pragma unroll
        for (int p = 1; p < 49; p++) { mpos = fmaxf(mpos, S[p]); mneg = fminf(mneg, S[p]); }
        const float m = 4.0f * mpos - 3.0f * mneg;   // >= every logit

        float* Ar = &s_att[SA_OFF + t * 49];
#pragma unroll
        for (int p = 0; p < 49; p++) Ar[p] = 0.f;

        // templates (compile-time constants -> immediate FFMAs)
        const float tw[9][9] = {
            {NORW,NORW,NORW, NORW,CNORW,NORW, NORW,NORW,NORW},
            {NEGW,POSW,NEGW, NEGW,POSW,NEGW, NEGW,POSW,NEGW},
            {NEGW,NEGW,NEGW, POSW,POSW,POSW, NEGW,NEGW,NEGW},
            {POSW,NEGW,NEGW, NEGW,POSW,NEGW, NEGW,NEGW,POSW},
            {NEGW,NEGW,POSW, NEGW,POSW,NEGW, POSW,NEGW,NEGW},
            {NEGW,POSW,NEGW, POSW,POSW,NEGW, NEGW,NEGW,NEGW},
            {NEGW,POSW,NEGW, NEGW,POSW,POSW, NEGW,NEGW,NEGW},
            {NEGW,NEGW,NEGW, POSW,POSW,NEGW, NEGW,POSW,NEGW},
            {NEGW,NEGW,NEGW, NEGW,POSW,POSW, NEGW,POSW,NEGW}
        };

        float ssum = 0.f;
#pragma unroll
        for (int ky = 0; ky < 5; ky++) {
#pragma unroll
            for (int kx = 0; kx < 5; kx++) {
                float e[9];
#pragma unroll
                for (int i = 0; i < 9; i++) {
                    float l = 0.f;
#pragma unroll
                    for (int a = 0; a < 3; a++)
#pragma unroll
                        for (int bb = 0; bb < 3; bb++)
                            l += tw[i][a*3+bb] * S[(ky + a) * 7 + kx + bb];
                    const float ev = __expf(l - m);
                    e[i] = ev;
                    ssum += ev;
                }
                // collapse 9 template weights back onto the 3x3 neighborhood
#pragma unroll
                for (int a = 0; a < 3; a++)
#pragma unroll
                    for (int bb = 0; bb < 3; bb++) {
                        float tv = 0.f;
#pragma unroll
                        for (int i = 0; i < 9; i++) tv += e[i] * tw[i][a*3+bb];
                        Ar[(ky + a) * 7 + kx + bb] += tv;
                    }
            }
        }

        const float inv = 1.0f / ssum;
        float o[32];
#pragma unroll
        for (int c = 0; c < 32; c++) o[c] = 0.f;
#pragma unroll
        for (int p = 0; p < 49; p++) {
            const float a = Ar[p];
#pragma unroll
            for (int c4 = 0; c4 < 8; c4++) {
                float4 vv = *(const float4*)&s_att[SV_OFF + p * QROW + cb + c4 * 4];
                o[c4*4+0] += a * vv.x; o[c4*4+1] += a * vv.y;
                o[c4*4+2] += a * vv.z; o[c4*4+3] += a * vv.w;
            }
        }

        const int qy = q / 5, qx = q % 5;
        float* dst = &g_y[((size_t)b * SP + (wy*5 + qy) * WWID + (wx*5 + qx)) * CDIM + cb];
#pragma unroll
        for (int c4 = 0; c4 < 8; c4++) {
            *(float4*)&dst[c4 * 4] = make_float4(o[c4*4+0]*inv, o[c4*4+1]*inv,
                                                 o[c4*4+2]*inv, o[c4*4+3]*inv);
        }
    }
}

// ---------------------------------------------------------------------------
// Kernel 3: output projection  out[b][c][p] = sum_k g_y[b][p][k] Wout[c][k] + bout[c]
// ---------------------------------------------------------------------------
__global__ __launch_bounds__(256) void outproj_kernel(
    const float* __restrict__ Wout,
    const float* __restrict__ bout,
    float* __restrict__ out)
{
    __shared__ float As[16][68];   // [k][p] (transposed on load)
    __shared__ float Bs[16][68];   // [k][c]

    const int p0 = blockIdx.x * 64;
    const int c0 = blockIdx.y * 64;
    const int b  = blockIdx.z;
    const int t  = threadIdx.x;
    const int tx = t & 15;      // p quad
    const int ty = t >> 4;      // c quad
    const int lpp = t >> 2, lkq = t & 3;    // A-tile load
    const int lcc = t >> 2;                 // B-tile load

    float acc[4][4];            // [c][p]
#pragma unroll
    for (int j = 0; j < 4; j++)
#pragma unroll
        for (int i = 0; i < 4; i++) acc[j][i] = 0.f;

    for (int kt = 0; kt < CDIM; kt += 16) {
        float4 a4 = *(const float4*)&g_y[((size_t)b * SP + p0 + lpp) * CDIM + kt + lkq * 4];
        As[lkq*4+0][lpp] = a4.x; As[lkq*4+1][lpp] = a4.y;
        As[lkq*4+2][lpp] = a4.z; As[lkq*4+3][lpp] = a4.w;

        float4 b4 = *(const float4*)&Wout[(c0 + lcc) * CDIM + kt + lkq * 4];
        Bs[lkq*4+0][lcc] = b4.x; Bs[lkq*4+1][lcc] = b4.y;
        Bs[lkq*4+2][lcc] = b4.z; Bs[lkq*4+3][lcc] = b4.w;
        __syncthreads();

#pragma unroll
        for (int kk = 0; kk < 16; kk++) {
            float4 a = *(const float4*)&As[kk][tx * 4];
            float4 c = *(const float4*)&Bs[kk][ty * 4];
            const float ar[4] = {a.x, a.y, a.z, a.w};
            const float cr[4] = {c.x, c.y, c.z, c.w};
#pragma unroll
            for (int j = 0; j < 4; j++)
#pragma unroll
                for (int i = 0; i < 4; i++)
                    acc[j][i] += cr[j] * ar[i];
        }
        __syncthreads();
    }

#pragma unroll
    for (int j = 0; j < 4; j++) {
        const int c = c0 + ty * 4 + j;
        const float bias = bout[c];
        *(float4*)&out[((size_t)b * CDIM + c) * SP + p0 + tx * 4] =
            make_float4(acc[j][0] + bias, acc[j][1] + bias,
                        acc[j][2] + bias, acc[j][3] + bias);
    }
}

// ---------------------------------------------------------------------------
extern "C" void kernel_launch(void* const* d_in, const int* in_sizes, int n_in,
                              void* d_out, int out_size)
{
    const float* x    = (const float*)d_in[0];
    // d_in[1] = conv_w: templates are fixed constants, hardcoded above.
    const float* Wk   = (const float*)d_in[2];
    const float* Wv   = (const float*)d_in[3];
    const float* Wq   = (const float*)d_in[4];
    const float* Wout = (const float*)d_in[5];
    const float* bout = (const float*)d_in[6];
    float* out = (float*)d_out;

    cudaFuncSetAttribute(attn_kernel, cudaFuncAttributeMaxDynamicSharedMemorySize,
                         ATT_SMEM_BYTES);

    proj3_kernel<<<dim3(SP / 64, CDIM / 64, BATCH), 256>>>(x, Wk, Wv, Wq);
    attn_kernel<<<NWIN, 256, ATT_SMEM_BYTES>>>();
    outproj_kernel<<<dim3(SP / 64, CDIM / 64, BATCH), 256>>>(Wout, bout, out);
}

// round 2
// speedup vs baseline: 1.4939x; 1.4939x over previous
#include <cuda_runtime.h>
#include <cuda_bf16.h>
#include <stdint.h>

#define BATCH 4
#define CDIM  256
#define HH    120
#define WWID  120
#define SP    (HH*WWID)
#define NB    24
#define NWIN  (BATCH*NB*NB)       // 2304
#define NPOS  (BATCH*SP)          // 57600
#define QSCALE 0.17677669529663688f

#define NEGW  (-0.5f)
#define POSW  (4.0f/3.0f)
#define NORW  (-0.375f)
#define CNORW (4.0f)

// fp32 projections (read by attn)
__device__ float g_xk[NPOS*CDIM];
__device__ float g_xv[NPOS*CDIM];
__device__ float g_xq[NPOS*CDIM];
// bf16 split inputs for MMA
__device__ __nv_bfloat16 g_xh[NPOS*CDIM];
__device__ __nv_bfloat16 g_xl[NPOS*CDIM];
__device__ __nv_bfloat16 g_yh[NPOS*CDIM];
__device__ __nv_bfloat16 g_yl[NPOS*CDIM];
__device__ __nv_bfloat16 g_wh[4*CDIM*CDIM];   // Wk,Wv,Wq,Wout
__device__ __nv_bfloat16 g_wl[4*CDIM*CDIM];

__device__ __forceinline__ uint32_t sptr(const void* p) {
    return (uint32_t)__cvta_generic_to_shared(p);
}

#define LDM_X4(R, A) asm volatile( \
    "ldmatrix.sync.aligned.m8n8.x4.shared.b16 {%0,%1,%2,%3}, [%4];" \
    : "=r"((R)[0]), "=r"((R)[1]), "=r"((R)[2]), "=r"((R)[3]) : "r"(A))

#define MMA_BF16(D, A, B0, B1) asm volatile( \
    "mma.sync.aligned.m16n8k16.row.col.f32.bf16.bf16.f32 " \
    "{%0,%1,%2,%3},{%4,%5,%6,%7},{%8,%9},{%0,%1,%2,%3};" \
    : "+f"((D)[0]), "+f"((D)[1]), "+f"((D)[2]), "+f"((D)[3]) \
    : "r"((A)[0]), "r"((A)[1]), "r"((A)[2]), "r"((A)[3]), "r"(B0), "r"(B1))

// ---------------------------------------------------------------------------
// Convert x [b][k][p] fp32 -> g_xh/g_xl [b*SP + p][k] bf16 hi/lo (transpose)
// ---------------------------------------------------------------------------
__global__ __launch_bounds__(256) void convertX_kernel(const float* __restrict__ x)
{
    __shared__ float st[64][65];
    const int p0 = blockIdx.x * 64;
    const int k0 = blockIdx.y * 64;
    const int b  = blockIdx.z;
    const int t  = threadIdx.x;

    for (int idx = t; idx < 4096; idx += 256) {
        const int k = idx >> 6, p = idx & 63;
        st[k][p] = x[((size_t)b * CDIM + k0 + k) * SP + p0 + p];
    }
    __syncthreads();
    for (int idx = t; idx < 2048; idx += 256) {
        const int p = idx >> 5, kk = idx & 31, k = kk * 2;
        const float v0 = st[k][p], v1 = st[k + 1][p];
        const __nv_bfloat16 h0 = __float2bfloat16(v0);
        const __nv_bfloat16 h1 = __float2bfloat16(v1);
        const __nv_bfloat16 l0 = __float2bfloat16(v0 - __bfloat162float(h0));
        const __nv_bfloat16 l1 = __float2bfloat16(v1 - __bfloat162float(h1));
        const size_t o = ((size_t)b * SP + p0 + p) * CDIM + k0 + k;
        *(__nv_bfloat162*)&g_xh[o] = __halves2bfloat162(h0, h1);
        *(__nv_bfloat162*)&g_xl[o] = __halves2bfloat162(l0, l1);
    }
}

// ---------------------------------------------------------------------------
// Convert the 4 weight matrices [c][k] -> bf16 hi/lo
// ---------------------------------------------------------------------------
__global__ __launch_bounds__(256) void convertW_kernel(
    const float* __restrict__ Wk, const float* __restrict__ Wv,
    const float* __restrict__ Wq, const float* __restrict__ Wout)
{
    const int i = blockIdx.x * 256 + threadIdx.x;   // 0..65535
    const float* srcs[4] = {Wk, Wv, Wq, Wout};
#pragma unroll
    for (int m = 0; m < 4; m++) {
        const float v = srcs[m][i];
        const __nv_bfloat16 h = __float2bfloat16(v);
        g_wh[m * 65536 + i] = h;
        g_wl[m * 65536 + i] = __float2bfloat16(v - __bfloat162float(h));
    }
}

// ---------------------------------------------------------------------------
// proj3 via mma.sync bf16 split: D[p, c] for K/V/Q.  M=128, N=64, KC=64.
// 8 warps: wm = warp/2 (M 32-strip), wn = warp%2 (N 32-strip).
// ---------------------------------------------------------------------------
#define PROJ_SMEM_HALVES (18432 + 27648)     // A(2*9216) + B(6*4608)
__global__ __launch_bounds__(256) void proj_mma_kernel()
{
    extern __shared__ __nv_bfloat16 sm[];
    __nv_bfloat16* sAh = sm;
    __nv_bfloat16* sAl = sm + 9216;
    __nv_bfloat16* sBh = sm + 18432;
    __nv_bfloat16* sBl = sm + 18432 + 13824;

    const int t = threadIdx.x;
    const int warp = t >> 5, lane = t & 31;
    const int wm = warp >> 1, wn = warp & 1;
    const int row0 = blockIdx.x * 128;
    const int c0   = blockIdx.y * 64;

    float acc[3][2][4][4];
#pragma unroll
    for (int a = 0; a < 3; a++)
#pragma unroll
        for (int b = 0; b < 2; b++)
#pragma unroll
            for (int c = 0; c < 4; c++)
#pragma unroll
                for (int d = 0; d < 4; d++) acc[a][b][c][d] = 0.f;

    for (int ch = 0; ch < 4; ch++) {
        const int kc = ch * 64;
        __syncthreads();
        for (int i = t; i < 1024; i += 256) {
            const int r = i >> 3, seg = i & 7;
            const size_t gi = (size_t)(row0 + r) * CDIM + kc + seg * 8;
            *(uint4*)&sAh[r * 72 + seg * 8] = *(const uint4*)&g_xh[gi];
            *(uint4*)&sAl[r * 72 + seg * 8] = *(const uint4*)&g_xl[gi];
        }
        for (int i = t; i < 1536; i += 256) {
            const int pr = i >> 9, rr = (i >> 3) & 63, seg = i & 7;
            const size_t gi = (size_t)pr * 65536 + (size_t)(c0 + rr) * CDIM + kc + seg * 8;
            *(uint4*)&sBh[pr * 4608 + rr * 72 + seg * 8] = *(const uint4*)&g_wh[gi];
            *(uint4*)&sBl[pr * 4608 + rr * 72 + seg * 8] = *(const uint4*)&g_wl[gi];
        }
        __syncthreads();

#pragma unroll
        for (int ks = 0; ks < 4; ks++) {
            uint32_t Ah[2][4], Al[2][4];
            const int colh = ks * 16 + ((lane >> 4) << 3);
#pragma unroll
            for (int mt = 0; mt < 2; mt++) {
                const int r = wm * 32 + mt * 16 + (lane & 15);
                LDM_X4(Ah[mt], sptr(&sAh[r * 72 + colh]));
                LDM_X4(Al[mt], sptr(&sAl[r * 72 + colh]));
            }
#pragma unroll
            for (int pr = 0; pr < 3; pr++) {
#pragma unroll
                for (int pair = 0; pair < 2; pair++) {
                    const int nr = wn * 32 + pair * 16 + (lane & 15);
                    uint32_t bh[4], bl[4];
                    LDM_X4(bh, sptr(&sBh[pr * 4608 + nr * 72 + colh]));
                    LDM_X4(bl, sptr(&sBl[pr * 4608 + nr * 72 + colh]));
#pragma unroll
                    for (int mt = 0; mt < 2; mt++) {
#pragma unroll
                        for (int sub = 0; sub < 2; sub++) {
                            const int nt = pair * 2 + sub;
                            MMA_BF16(acc[pr][mt][nt], Ah[mt], bh[sub], bh[sub + 2]);
                            MMA_BF16(acc[pr][mt][nt], Ah[mt], bl[sub], bl[sub + 2]);
                            MMA_BF16(acc[pr][mt][nt], Al[mt], bh[sub], bh[sub + 2]);
                        }
                    }
                }
            }
        }
    }

    const int rbase = row0 + wm * 32 + (lane >> 2);
    const int cbase = c0 + wn * 32 + (lane & 3) * 2;
    float* dsts[3] = {g_xk, g_xv, g_xq};
#pragma unroll
    for (int pr = 0; pr < 3; pr++) {
        const float s = (pr == 2) ? QSCALE : 1.f;
#pragma unroll
        for (int mt = 0; mt < 2; mt++) {
#pragma unroll
            for (int nt = 0; nt < 4; nt++) {
                const int r = rbase + mt * 16;
                const int c = cbase + nt * 8;
                float* d = dsts[pr];
                *(float2*)&d[(size_t)r * CDIM + c] =
                    make_float2(acc[pr][mt][nt][0] * s, acc[pr][mt][nt][1] * s);
                *(float2*)&d[(size_t)(r + 8) * CDIM + c] =
                    make_float2(acc[pr][mt][nt][2] * s, acc[pr][mt][nt][3] * s);
            }
        }
    }
}

// ---------------------------------------------------------------------------
// attn: CTA = (window, head-half). 128 threads; t<100 compute (4 heads x 25 q).
// K/V staged per-head [hl][p][36] (bank-conflict-free), Q direct from global.
// Ar accumulator in registers. Output written as bf16 hi/lo for outproj MMA.
// ---------------------------------------------------------------------------
#define ATTN_SMEM_BYTES (2 * 4 * 49 * 36 * 4)
__global__ __launch_bounds__(128) void attn_kernel()
{
    extern __shared__ float sm_att[];
    float* sK = sm_att;
    float* sV = sm_att + 4 * 49 * 36;

    const int blk  = blockIdx.x;
    const int half = blockIdx.y;
    const int b    = blk / (NB * NB);
    const int wrem = blk % (NB * NB);
    const int wy = wrem / NB, wx = wrem % NB;
    const int t = threadIdx.x;
    const int c0 = half * 128;

    const int ky0 = wy * 5 - 1, kx0 = wx * 5 - 1;
    for (int idx = t; idx < 49 * 32; idx += 128) {
        const int r  = idx >> 5;
        const int c4 = idx & 31;
        const int y  = ky0 + r / 7;
        const int xx = kx0 + r % 7;
        float4 vk = make_float4(0.f, 0.f, 0.f, 0.f);
        float4 vv = make_float4(0.f, 0.f, 0.f, 0.f);
        if (y >= 0 && y < HH && xx >= 0 && xx < WWID) {
            const size_t g = ((size_t)b * SP + y * WWID + xx) * CDIM + c0 + c4 * 4;
            vk = *(const float4*)&g_xk[g];
            vv = *(const float4*)&g_xv[g];
        }
        const int f = c4 * 4, hl = f >> 5, cc = f & 31;
        *(float4*)&sK[(hl * 49 + r) * 36 + cc] = vk;
        *(float4*)&sV[(hl * 49 + r) * 36 + cc] = vv;
    }
    __syncthreads();

    if (t < 100) {
        const int hl = t / 25, q = t % 25;
        const int hg = half * 4 + hl;
        const int qy = q / 5, qx = q % 5;
        const size_t qpos = ((size_t)b * SP + (wy * 5 + qy) * WWID + wx * 5 + qx) * CDIM
                            + hg * 32;

        float qv[32];
#pragma unroll
        for (int c4 = 0; c4 < 8; c4++) {
            const float4 v = *(const float4*)&g_xq[qpos + c4 * 4];
            qv[c4*4+0] = v.x; qv[c4*4+1] = v.y; qv[c4*4+2] = v.z; qv[c4*4+3] = v.w;
        }

        float S[49];
#pragma unroll
        for (int p = 0; p < 49; p++) {
            float a0 = 0.f;
#pragma unroll
            for (int c4 = 0; c4 < 8; c4++) {
                const float4 kv = *(const float4*)&sK[(hl * 49 + p) * 36 + c4 * 4];
                a0 += qv[c4*4+0]*kv.x + qv[c4*4+1]*kv.y + qv[c4*4+2]*kv.z + qv[c4*4+3]*kv.w;
            }
            S[p] = a0;
        }

        float mpos = S[0], mneg = S[0];
#pragma unroll
        for (int p = 1; p < 49; p++) { mpos = fmaxf(mpos, S[p]); mneg = fminf(mneg, S[p]); }
        const float m = 4.0f * mpos - 3.0f * mneg;

        const float tw[9][9] = {
            {NORW,NORW,NORW, NORW,CNORW,NORW, NORW,NORW,NORW},
            {NEGW,POSW,NEGW, NEGW,POSW,NEGW, NEGW,POSW,NEGW},
            {NEGW,NEGW,NEGW, POSW,POSW,POSW, NEGW,NEGW,NEGW},
            {POSW,NEGW,NEGW, NEGW,POSW,NEGW, NEGW,NEGW,POSW},
            {NEGW,NEGW,POSW, NEGW,POSW,NEGW, POSW,NEGW,NEGW},
            {NEGW,POSW,NEGW, POSW,POSW,NEGW, NEGW,NEGW,NEGW},
            {NEGW,POSW,NEGW, NEGW,POSW,POSW, NEGW,NEGW,NEGW},
            {NEGW,NEGW,NEGW, POSW,POSW,NEGW, NEGW,POSW,NEGW},
            {NEGW,NEGW,NEGW, NEGW,POSW,POSW, NEGW,POSW,NEGW}
        };

        float Ar[49];
#pragma unroll
        for (int p = 0; p < 49; p++) Ar[p] = 0.f;

        float ssum = 0.f;
#pragma unroll
        for (int ky = 0; ky < 5; ky++) {
#pragma unroll
            for (int kx = 0; kx < 5; kx++) {
                float e[9];
#pragma unroll
                for (int i = 0; i < 9; i++) {
                    float l = 0.f;
#pragma unroll
                    for (int a = 0; a < 3; a++)
#pragma unroll
                        for (int bb = 0; bb < 3; bb++)
                            l += tw[i][a*3+bb] * S[(ky + a) * 7 + kx + bb];
                    const float ev = __expf(l - m);
                    e[i] = ev;
                    ssum += ev;
                }
#pragma unroll
                for (int a = 0; a < 3; a++)
#pragma unroll
                    for (int bb = 0; bb < 3; bb++) {
                        float tv = 0.f;
#pragma unroll
                        for (int i = 0; i < 9; i++) tv += e[i] * tw[i][a*3+bb];
                        Ar[(ky + a) * 7 + kx + bb] += tv;
                    }
            }
        }

        const float inv = 1.0f / ssum;
        float o[32];
#pragma unroll
        for (int c = 0; c < 32; c++) o[c] = 0.f;
#pragma unroll
        for (int p = 0; p < 49; p++) {
            const float a = Ar[p];
#pragma unroll
            for (int c4 = 0; c4 < 8; c4++) {
                const float4 vv = *(const float4*)&sV[(hl * 49 + p) * 36 + c4 * 4];
                o[c4*4+0] += a * vv.x; o[c4*4+1] += a * vv.y;
                o[c4*4+2] += a * vv.z; o[c4*4+3] += a * vv.w;
            }
        }

#pragma unroll
        for (int j = 0; j < 16; j++) {
            const float v0 = o[2*j]   * inv;
            const float v1 = o[2*j+1] * inv;
            const __nv_bfloat16 h0 = __float2bfloat16(v0);
            const __nv_bfloat16 h1 = __float2bfloat16(v1);
            const __nv_bfloat16 l0 = __float2bfloat16(v0 - __bfloat162float(h0));
            const __nv_bfloat16 l1 = __float2bfloat16(v1 - __bfloat162float(h1));
            *(__nv_bfloat162*)&g_yh[qpos + 2*j] = __halves2bfloat162(h0, h1);
            *(__nv_bfloat162*)&g_yl[qpos + 2*j] = __halves2bfloat162(l0, l1);
        }
    }
}

// ---------------------------------------------------------------------------
// outproj via mma.sync bf16 split; epilogue transposes through smem to NCHW.
// ---------------------------------------------------------------------------
#define OUTP_SMEM_BYTES ((18432 + 9216) * 2)     // >= 64*132*4 epilogue floats
__global__ __launch_bounds__(256) void outproj_mma_kernel(
    const float* __restrict__ bout, float* __restrict__ out)
{
    extern __shared__ __nv_bfloat16 sm[];
    __nv_bfloat16* sAh = sm;
    __nv_bfloat16* sAl = sm + 9216;
    __nv_bfloat16* sBh = sm + 18432;
    __nv_bfloat16* sBl = sm + 18432 + 4608;
    float* sT = (float*)sm;

    const int t = threadIdx.x;
    const int warp = t >> 5, lane = t & 31;
    const int wm = warp >> 1, wn = warp & 1;
    const int row0 = blockIdx.x * 128;
    const int c0   = blockIdx.y * 64;

    float acc[2][4][4];
#pragma unroll
    for (int b = 0; b < 2; b++)
#pragma unroll
        for (int c = 0; c < 4; c++)
#pragma unroll
            for (int d = 0; d < 4; d++) acc[b][c][d] = 0.f;

    for (int ch = 0; ch < 4; ch++) {
        const int kc = ch * 64;
        __syncthreads();
        for (int i = t; i < 1024; i += 256) {
            const int r = i >> 3, seg = i & 7;
            const size_t gi = (size_t)(row0 + r) * CDIM + kc + seg * 8;
            *(uint4*)&sAh[r * 72 + seg * 8] = *(const uint4*)&g_yh[gi];
            *(uint4*)&sAl[r * 72 + seg * 8] = *(const uint4*)&g_yl[gi];
        }
        for (int i = t; i < 512; i += 256) {
            const int rr = i >> 3, seg = i & 7;
            const size_t gi = (size_t)3 * 65536 + (size_t)(c0 + rr) * CDIM + kc + seg * 8;
            *(uint4*)&sBh[rr * 72 + seg * 8] = *(const uint4*)&g_wh[gi];
            *(uint4*)&sBl[rr * 72 + seg * 8] = *(const uint4*)&g_wl[gi];
        }
        __syncthreads();

#pragma unroll
        for (int ks = 0; ks < 4; ks++) {
            uint32_t Ah[2][4], Al[2][4];
            const int colh = ks * 16 + ((lane >> 4) << 3);
#pragma unroll
            for (int mt = 0; mt < 2; mt++) {
                const int r = wm * 32 + mt * 16 + (lane & 15);
                LDM_X4(Ah[mt], sptr(&sAh[r * 72 + colh]));
                LDM_X4(Al[mt], sptr(&sAl[r * 72 + colh]));
            }
#pragma unroll
            for (int pair = 0; pair < 2; pair++) {
                const int nr = wn * 32 + pair * 16 + (lane & 15);
                uint32_t bh[4], bl[4];
                LDM_X4(bh, sptr(&sBh[nr * 72 + colh]));
                LDM_X4(bl, sptr(&sBl[nr * 72 + colh]));
#pragma unroll
                for (int mt = 0; mt < 2; mt++) {
#pragma unroll
                    for (int sub = 0; sub < 2; sub++) {
                        const int nt = pair * 2 + sub;
                        MMA_BF16(acc[mt][nt], Ah[mt], bh[sub], bh[sub + 2]);
                        MMA_BF16(acc[mt][nt], Ah[mt], bl[sub], bl[sub + 2]);
                        MMA_BF16(acc[mt][nt], Al[mt], bh[sub], bh[sub + 2]);
                    }
                }
            }
        }
    }

    __syncthreads();   // done with bf16 smem; reuse as fp32 transpose buffer
    const int rl = wm * 32 + (lane >> 2);
    const int cl = wn * 32 + (lane & 3) * 2;
#pragma unroll
    for (int mt = 0; mt < 2; mt++) {
#pragma unroll
        for (int nt = 0; nt < 4; nt++) {
            const int r = rl + mt * 16;
            const int c = cl + nt * 8;
            sT[(c    ) * 132 + r    ] = acc[mt][nt][0];
            sT[(c + 1) * 132 + r    ] = acc[mt][nt][1];
            sT[(c    ) * 132 + r + 8] = acc[mt][nt][2];
            sT[(c + 1) * 132 + r + 8] = acc[mt][nt][3];
        }
    }
    __syncthreads();

    for (int i = t; i < 8192; i += 256) {
        const int c = i >> 7, r = i & 127;
        const int pf = row0 + r;
        const int b  = pf / SP;
        const int p  = pf - b * SP;
        out[((size_t)b * CDIM + c0 + c) * SP + p] = sT[c * 132 + r] + bout[c0 + c];
    }
}

// ---------------------------------------------------------------------------
extern "C" void kernel_launch(void* const* d_in, const int* in_sizes, int n_in,
                              void* d_out, int out_size)
{
    const float* x    = (const float*)d_in[0];
    const float* Wk   = (const float*)d_in[2];
    const float* Wv   = (const float*)d_in[3];
    const float* Wq   = (const float*)d_in[4];
    const float* Wout = (const float*)d_in[5];
    const float* bout = (const float*)d_in[6];
    float* out = (float*)d_out;

    cudaFuncSetAttribute(proj_mma_kernel, cudaFuncAttributeMaxDynamicSharedMemorySize,
                         PROJ_SMEM_HALVES * 2);
    cudaFuncSetAttribute(attn_kernel, cudaFuncAttributeMaxDynamicSharedMemorySize,
                         ATTN_SMEM_BYTES);
    cudaFuncSetAttribute(outproj_mma_kernel, cudaFuncAttributeMaxDynamicSharedMemorySize,
                         OUTP_SMEM_BYTES);

    convertX_kernel<<<dim3(SP / 64, CDIM / 64, BATCH), 256>>>(x);
    convertW_kernel<<<256, 256>>>(Wk, Wv, Wq, Wout);
    proj_mma_kernel<<<dim3(NPOS / 128, CDIM / 64), 256, PROJ_SMEM_HALVES * 2>>>();
    attn_kernel<<<dim3(NWIN, 2), 128, ATTN_SMEM_BYTES>>>();
    outproj_mma_kernel<<<dim3(NPOS / 128, CDIM / 64), 256, OUTP_SMEM_BYTES>>>(bout, out);
}

// round 4
// speedup vs baseline: 1.5940x; 1.0670x over previous
#include <cuda_runtime.h>
#include <cuda_bf16.h>
#include <stdint.h>

#define BATCH 4
#define CDIM  256
#define HH    120
#define WWID  120
#define SP    (HH*WWID)
#define NB    24
#define NWIN  (BATCH*NB*NB)       // 2304
#define NPOS  (BATCH*SP)          // 57600
#define QSCALE 0.17677669529663688f

#define NEGW  (-0.5f)
#define POSW  (4.0f/3.0f)
#define NORW  (-0.375f)
#define CNORW (4.0f)
#define PW    (1.8333333333333333f)   // POSW - NEGW
#define C0W   (4.375f)                // CNORW - NORW

// fp32 projections (read by attn)
__device__ float g_xk[NPOS*CDIM];
__device__ float g_xv[NPOS*CDIM];
__device__ float g_xq[NPOS*CDIM];
// bf16 split inputs for MMA
__device__ __nv_bfloat16 g_xh[NPOS*CDIM];
__device__ __nv_bfloat16 g_xl[NPOS*CDIM];
__device__ __nv_bfloat16 g_yh[NPOS*CDIM];
__device__ __nv_bfloat16 g_yl[NPOS*CDIM];
__device__ __nv_bfloat16 g_wh[4*CDIM*CDIM];   // Wk,Wv,Wq,Wout
__device__ __nv_bfloat16 g_wl[4*CDIM*CDIM];

__device__ __forceinline__ uint32_t sptr(const void* p) {
    return (uint32_t)__cvta_generic_to_shared(p);
}

#define LDM_X4(R, A) asm volatile( \
    "ldmatrix.sync.aligned.m8n8.x4.shared.b16 {%0,%1,%2,%3}, [%4];" \
    : "=r"((R)[0]), "=r"((R)[1]), "=r"((R)[2]), "=r"((R)[3]) : "r"(A))

#define MMA_BF16(D, A, B0, B1) asm volatile( \
    "mma.sync.aligned.m16n8k16.row.col.f32.bf16.bf16.f32 " \
    "{%0,%1,%2,%3},{%4,%5,%6,%7},{%8,%9},{%0,%1,%2,%3};" \
    : "+f"((D)[0]), "+f"((D)[1]), "+f"((D)[2]), "+f"((D)[3]) \
    : "r"((A)[0]), "r"((A)[1]), "r"((A)[2]), "r"((A)[3]), "r"(B0), "r"(B1))

// ---------------------------------------------------------------------------
// Convert x [b][k][p] fp32 -> g_xh/g_xl [b*SP + p][k] bf16 hi/lo (transpose)
// ---------------------------------------------------------------------------
__global__ __launch_bounds__(256) void convertX_kernel(const float* __restrict__ x)
{
    __shared__ float st[64][65];
    const int p0 = blockIdx.x * 64;
    const int k0 = blockIdx.y * 64;
    const int b  = blockIdx.z;
    const int t  = threadIdx.x;

    for (int idx = t; idx < 4096; idx += 256) {
        const int k = idx >> 6, p = idx & 63;
        st[k][p] = x[((size_t)b * CDIM + k0 + k) * SP + p0 + p];
    }
    __syncthreads();
    for (int idx = t; idx < 2048; idx += 256) {
        const int p = idx >> 5, kk = idx & 31, k = kk * 2;
        const float v0 = st[k][p], v1 = st[k + 1][p];
        const __nv_bfloat16 h0 = __float2bfloat16(v0);
        const __nv_bfloat16 h1 = __float2bfloat16(v1);
        const __nv_bfloat16 l0 = __float2bfloat16(v0 - __bfloat162float(h0));
        const __nv_bfloat16 l1 = __float2bfloat16(v1 - __bfloat162float(h1));
        const size_t o = ((size_t)b * SP + p0 + p) * CDIM + k0 + k;
        *(__nv_bfloat162*)&g_xh[o] = __halves2bfloat162(h0, h1);
        *(__nv_bfloat162*)&g_xl[o] = __halves2bfloat162(l0, l1);
    }
}

// ---------------------------------------------------------------------------
// Convert the 4 weight matrices [c][k] -> bf16 hi/lo
// ---------------------------------------------------------------------------
__global__ __launch_bounds__(256) void convertW_kernel(
    const float* __restrict__ Wk, const float* __restrict__ Wv,
    const float* __restrict__ Wq, const float* __restrict__ Wout)
{
    const int i = blockIdx.x * 256 + threadIdx.x;   // 0..65535
    const float* srcs[4] = {Wk, Wv, Wq, Wout};
#pragma unroll
    for (int m = 0; m < 4; m++) {
        const float v = srcs[m][i];
        const __nv_bfloat16 h = __float2bfloat16(v);
        g_wh[m * 65536 + i] = h;
        g_wl[m * 65536 + i] = __float2bfloat16(v - __bfloat162float(h));
    }
}

// ---------------------------------------------------------------------------
// proj3 via mma.sync bf16 split: D[p, c] for K/V/Q.  M=128, N=64, KC=64.
// 8 warps: wm = warp/2 (M 32-strip), wn = warp%2 (N 32-strip).
// ---------------------------------------------------------------------------
#define PROJ_SMEM_HALVES (18432 + 27648)     // A(2*9216) + B(6*4608)
__global__ __launch_bounds__(256) void proj_mma_kernel()
{
    extern __shared__ __nv_bfloat16 sm[];
    __nv_bfloat16* sAh = sm;
    __nv_bfloat16* sAl = sm + 9216;
    __nv_bfloat16* sBh = sm + 18432;
    __nv_bfloat16* sBl = sm + 18432 + 13824;

    const int t = threadIdx.x;
    const int warp = t >> 5, lane = t & 31;
    const int wm = warp >> 1, wn = warp & 1;
    const int row0 = blockIdx.x * 128;
    const int c0   = blockIdx.y * 64;

    float acc[3][2][4][4];
#pragma unroll
    for (int a = 0; a < 3; a++)
#pragma unroll
        for (int b = 0; b < 2; b++)
#pragma unroll
            for (int c = 0; c < 4; c++)
#pragma unroll
                for (int d = 0; d < 4; d++) acc[a][b][c][d] = 0.f;

    for (int ch = 0; ch < 4; ch++) {
        const int kc = ch * 64;
        __syncthreads();
        for (int i = t; i < 1024; i += 256) {
            const int r = i >> 3, seg = i & 7;
            const size_t gi = (size_t)(row0 + r) * CDIM + kc + seg * 8;
            *(uint4*)&sAh[r * 72 + seg * 8] = *(const uint4*)&g_xh[gi];
            *(uint4*)&sAl[r * 72 + seg * 8] = *(const uint4*)&g_xl[gi];
        }
        for (int i = t; i < 1536; i += 256) {
            const int pr = i >> 9, rr = (i >> 3) & 63, seg = i & 7;
            const size_t gi = (size_t)pr * 65536 + (size_t)(c0 + rr) * CDIM + kc + seg * 8;
            *(uint4*)&sBh[pr * 4608 + rr * 72 + seg * 8] = *(const uint4*)&g_wh[gi];
            *(uint4*)&sBl[pr * 4608 + rr * 72 + seg * 8] = *(const uint4*)&g_wl[gi];
        }
        __syncthreads();

#pragma unroll
        for (int ks = 0; ks < 4; ks++) {
            uint32_t Ah[2][4], Al[2][4];
            const int colh = ks * 16 + ((lane >> 4) << 3);
#pragma unroll
            for (int mt = 0; mt < 2; mt++) {
                const int r = wm * 32 + mt * 16 + (lane & 15);
                LDM_X4(Ah[mt], sptr(&sAh[r * 72 + colh]));
                LDM_X4(Al[mt], sptr(&sAl[r * 72 + colh]));
            }
#pragma unroll
            for (int pr = 0; pr < 3; pr++) {
#pragma unroll
                for (int pair = 0; pair < 2; pair++) {
                    const int nr = wn * 32 + pair * 16 + (lane & 15);
                    uint32_t bh[4], bl[4];
                    LDM_X4(bh, sptr(&sBh[pr * 4608 + nr * 72 + colh]));
                    LDM_X4(bl, sptr(&sBl[pr * 4608 + nr * 72 + colh]));
#pragma unroll
                    for (int mt = 0; mt < 2; mt++) {
#pragma unroll
                        for (int sub = 0; sub < 2; sub++) {
                            const int nt = pair * 2 + sub;
                            MMA_BF16(acc[pr][mt][nt], Ah[mt], bh[sub], bh[sub + 2]);
                            MMA_BF16(acc[pr][mt][nt], Ah[mt], bl[sub], bl[sub + 2]);
                            MMA_BF16(acc[pr][mt][nt], Al[mt], bh[sub], bh[sub + 2]);
                        }
                    }
                }
            }
        }
    }

    const int rbase = row0 + wm * 32 + (lane >> 2);
    const int cbase = c0 + wn * 32 + (lane & 3) * 2;
    float* dsts[3] = {g_xk, g_xv, g_xq};
#pragma unroll
    for (int pr = 0; pr < 3; pr++) {
        const float s = (pr == 2) ? QSCALE : 1.f;
#pragma unroll
        for (int mt = 0; mt < 2; mt++) {
#pragma unroll
            for (int nt = 0; nt < 4; nt++) {
                const int r = rbase + mt * 16;
                const int c = cbase + nt * 8;
                float* d = dsts[pr];
                *(float2*)&d[(size_t)r * CDIM + c] =
                    make_float2(acc[pr][mt][nt][0] * s, acc[pr][mt][nt][1] * s);
                *(float2*)&d[(size_t)(r + 8) * CDIM + c] =
                    make_float2(acc[pr][mt][nt][2] * s, acc[pr][mt][nt][3] * s);
            }
        }
    }
}

// ---------------------------------------------------------------------------
// attn: CTA = (window, head-half). 128 threads; t<100 compute (4 heads x 25 q).
// Sparse-template algebra: tw_i = NEGW*ones + PW*(3-tap), t0 = NORW*ones + C0W*c.
// ---------------------------------------------------------------------------
#define ATTN_SMEM_BYTES (2 * 4 * 49 * 36 * 4)
__global__ __launch_bounds__(128) void attn_kernel()
{
    extern __shared__ float sm_att[];
    float* sK = sm_att;
    float* sV = sm_att + 4 * 49 * 36;

    const int blk  = blockIdx.x;
    const int half = blockIdx.y;
    const int b    = blk / (NB * NB);
    const int wrem = blk % (NB * NB);
    const int wy = wrem / NB, wx = wrem % NB;
    const int t = threadIdx.x;
    const int c0 = half * 128;

    const int ky0 = wy * 5 - 1, kx0 = wx * 5 - 1;
    for (int idx = t; idx < 49 * 32; idx += 128) {
        const int r  = idx >> 5;
        const int c4 = idx & 31;
        const int y  = ky0 + r / 7;
        const int xx = kx0 + r % 7;
        float4 vk = make_float4(0.f, 0.f, 0.f, 0.f);
        float4 vv = make_float4(0.f, 0.f, 0.f, 0.f);
        if (y >= 0 && y < HH && xx >= 0 && xx < WWID) {
            const size_t g = ((size_t)b * SP + y * WWID + xx) * CDIM + c0 + c4 * 4;
            vk = *(const float4*)&g_xk[g];
            vv = *(const float4*)&g_xv[g];
        }
        const int f = c4 * 4, hl = f >> 5, cc = f & 31;
        *(float4*)&sK[(hl * 49 + r) * 36 + cc] = vk;
        *(float4*)&sV[(hl * 49 + r) * 36 + cc] = vv;
    }
    __syncthreads();

    if (t < 100) {
        const int hl = t / 25, q = t % 25;
        const int hg = half * 4 + hl;
        const int qy = q / 5, qx = q % 5;
        const size_t qpos = ((size_t)b * SP + (wy * 5 + qy) * WWID + wx * 5 + qx) * CDIM
                            + hg * 32;

        float qv[32];
#pragma unroll
        for (int c4 = 0; c4 < 8; c4++) {
            const float4 v = *(const float4*)&g_xq[qpos + c4 * 4];
            qv[c4*4+0] = v.x; qv[c4*4+1] = v.y; qv[c4*4+2] = v.z; qv[c4*4+3] = v.w;
        }

        float S[49];
#pragma unroll
        for (int p = 0; p < 49; p++) {
            float a0 = 0.f;
#pragma unroll
            for (int c4 = 0; c4 < 8; c4++) {
                const float4 kv = *(const float4*)&sK[(hl * 49 + p) * 36 + c4 * 4];
                a0 += qv[c4*4+0]*kv.x + qv[c4*4+1]*kv.y + qv[c4*4+2]*kv.z + qv[c4*4+3]*kv.w;
            }
            S[p] = a0;
        }

        float mpos = S[0], mneg = S[0];
#pragma unroll
        for (int p = 1; p < 49; p++) { mpos = fmaxf(mpos, S[p]); mneg = fminf(mneg, S[p]); }
        const float m = 4.0f * mpos - 3.0f * mneg;

        float Ar[49];
#pragma unroll
        for (int p = 0; p < 49; p++) Ar[p] = 0.f;

        float ssum = 0.f;
#pragma unroll
        for (int ky = 0; ky < 5; ky++) {
#pragma unroll
            for (int kx = 0; kx < 5; kx++) {
                const float c  = S[(ky+1)*7 + kx+1];
                const float u  = S[(ky  )*7 + kx+1];
                const float d  = S[(ky+2)*7 + kx+1];
                const float l  = S[(ky+1)*7 + kx  ];
                const float r  = S[(ky+1)*7 + kx+2];
                const float tl = S[(ky  )*7 + kx  ];
                const float tr = S[(ky  )*7 + kx+2];
                const float bl = S[(ky+2)*7 + kx  ];
                const float br = S[(ky+2)*7 + kx+2];
                const float s_ud = u + d, s_lr = l + r;
                const float dg = tl + br, ad = tr + bl;
                const float sum9 = ((s_ud + s_lr) + (dg + ad)) + c;
                const float base = fmaf(NEGW, sum9, -m);
                const float e0 = __expf(fmaf(NORW, sum9, fmaf(C0W, c, -m)));
                const float e1 = __expf(fmaf(PW, s_ud + c, base));
                const float e2 = __expf(fmaf(PW, s_lr + c, base));
                const float e3 = __expf(fmaf(PW, dg + c, base));
                const float e4 = __expf(fmaf(PW, ad + c, base));
                const float e5 = __expf(fmaf(PW, (u + l) + c, base));
                const float e6 = __expf(fmaf(PW, (u + r) + c, base));
                const float e7 = __expf(fmaf(PW, (l + d) + c, base));
                const float e8 = __expf(fmaf(PW, (r + d) + c, base));
                const float E = ((e1 + e2) + (e3 + e4)) + ((e5 + e6) + (e7 + e8));
                ssum += E + e0;
                const float basea = fmaf(NEGW, E, NORW * e0);
                Ar[(ky  )*7 + kx  ] += fmaf(PW, e3, basea);
                Ar[(ky  )*7 + kx+1] += fmaf(PW, (e1 + e5) + e6, basea);
                Ar[(ky  )*7 + kx+2] += fmaf(PW, e4, basea);
                Ar[(ky+1)*7 + kx  ] += fmaf(PW, (e2 + e5) + e7, basea);
                Ar[(ky+1)*7 + kx+1] += fmaf(PW, E, fmaf(C0W, e0, basea));
                Ar[(ky+1)*7 + kx+2] += fmaf(PW, (e2 + e6) + e8, basea);
                Ar[(ky+2)*7 + kx  ] += fmaf(PW, e4, basea);
                Ar[(ky+2)*7 + kx+1] += fmaf(PW, (e1 + e7) + e8, basea);
                Ar[(ky+2)*7 + kx+2] += fmaf(PW, e3, basea);
            }
        }

        const float inv = 1.0f / ssum;
        float o[32];
#pragma unroll
        for (int c = 0; c < 32; c++) o[c] = 0.f;
#pragma unroll
        for (int p = 0; p < 49; p++) {
            const float a = Ar[p];
#pragma unroll
            for (int c4 = 0; c4 < 8; c4++) {
                const float4 vv = *(const float4*)&sV[(hl * 49 + p) * 36 + c4 * 4];
                o[c4*4+0] += a * vv.x; o[c4*4+1] += a * vv.y;
                o[c4*4+2] += a * vv.z; o[c4*4+3] += a * vv.w;
            }
        }

#pragma unroll
        for (int j = 0; j < 16; j++) {
            const float v0 = o[2*j]   * inv;
            const float v1 = o[2*j+1] * inv;
            const __nv_bfloat16 h0 = __float2bfloat16(v0);
            const __nv_bfloat16 h1 = __float2bfloat16(v1);
            const __nv_bfloat16 l0 = __float2bfloat16(v0 - __bfloat162float(h0));
            const __nv_bfloat16 l1 = __float2bfloat16(v1 - __bfloat162float(h1));
            *(__nv_bfloat162*)&g_yh[qpos + 2*j] = __halves2bfloat162(h0, h1);
            *(__nv_bfloat162*)&g_yl[qpos + 2*j] = __halves2bfloat162(l0, l1);
        }
    }
}

// ---------------------------------------------------------------------------
// outproj via mma.sync bf16 split; epilogue transposes through smem to NCHW.
// ---------------------------------------------------------------------------
#define OUTP_SMEM_BYTES ((18432 + 9216) * 2)     // >= 64*132*4 epilogue floats
__global__ __launch_bounds__(256) void outproj_mma_kernel(
    const float* __restrict__ bout, float* __restrict__ out)
{
    extern __shared__ __nv_bfloat16 sm[];
    __nv_bfloat16* sAh = sm;
    __nv_bfloat16* sAl = sm + 9216;
    __nv_bfloat16* sBh = sm + 18432;
    __nv_bfloat16* sBl = sm + 18432 + 4608;
    float* sT = (float*)sm;

    const int t = threadIdx.x;
    const int warp = t >> 5, lane = t & 31;
    const int wm = warp >> 1, wn = warp & 1;
    const int row0 = blockIdx.x * 128;
    const int c0   = blockIdx.y * 64;

    float acc[2][4][4];
#pragma unroll
    for (int b = 0; b < 2; b++)
#pragma unroll
        for (int c = 0; c < 4; c++)
#pragma unroll
            for (int d = 0; d < 4; d++) acc[b][c][d] = 0.f;

    for (int ch = 0; ch < 4; ch++) {
        const int kc = ch * 64;
        __syncthreads();
        for (int i = t; i < 1024; i += 256) {
            const int r = i >> 3, seg = i & 7;
            const size_t gi = (size_t)(row0 + r) * CDIM + kc + seg * 8;
            *(uint4*)&sAh[r * 72 + seg * 8] = *(const uint4*)&g_yh[gi];
            *(uint4*)&sAl[r * 72 + seg * 8] = *(const uint4*)&g_yl[gi];
        }
        for (int i = t; i < 512; i += 256) {
            const int rr = i >> 3, seg = i & 7;
            const size_t gi = (size_t)3 * 65536 + (size_t)(c0 + rr) * CDIM + kc + seg * 8;
            *(uint4*)&sBh[rr * 72 + seg * 8] = *(const uint4*)&g_wh[gi];
            *(uint4*)&sBl[rr * 72 + seg * 8] = *(const uint4*)&g_wl[gi];
        }
        __syncthreads();

#pragma unroll
        for (int ks = 0; ks < 4; ks++) {
            uint32_t Ah[2][4], Al[2][4];
            const int colh = ks * 16 + ((lane >> 4) << 3);
#pragma unroll
            for (int mt = 0; mt < 2; mt++) {
                const int r = wm * 32 + mt * 16 + (lane & 15);
                LDM_X4(Ah[mt], sptr(&sAh[r * 72 + colh]));
                LDM_X4(Al[mt], sptr(&sAl[r * 72 + colh]));
            }
#pragma unroll
            for (int pair = 0; pair < 2; pair++) {
                const int nr = wn * 32 + pair * 16 + (lane & 15);
                uint32_t bh[4], bl[4];
                LDM_X4(bh, sptr(&sBh[nr * 72 + colh]));
                LDM_X4(bl, sptr(&sBl[nr * 72 + colh]));
#pragma unroll
                for (int mt = 0; mt < 2; mt++) {
#pragma unroll
                    for (int sub = 0; sub < 2; sub++) {
                        const int nt = pair * 2 + sub;
                        MMA_BF16(acc[mt][nt], Ah[mt], bh[sub], bh[sub + 2]);
                        MMA_BF16(acc[mt][nt], Ah[mt], bl[sub], bl[sub + 2]);
                        MMA_BF16(acc[mt][nt], Al[mt], bh[sub], bh[sub + 2]);
                    }
                }
            }
        }
    }

    __syncthreads();   // done with bf16 smem; reuse as fp32 transpose buffer
    const int rl = wm * 32 + (lane >> 2);
    const int cl = wn * 32 + (lane & 3) * 2;
#pragma unroll
    for (int mt = 0; mt < 2; mt++) {
#pragma unroll
        for (int nt = 0; nt < 4; nt++) {
            const int r = rl + mt * 16;
            const int c = cl + nt * 8;
            sT[(c    ) * 132 + r    ] = acc[mt][nt][0];
            sT[(c + 1) * 132 + r    ] = acc[mt][nt][1];
            sT[(c    ) * 132 + r + 8] = acc[mt][nt][2];
            sT[(c + 1) * 132 + r + 8] = acc[mt][nt][3];
        }
    }
    __syncthreads();

    for (int i = t; i < 8192; i += 256) {
        const int c = i >> 7, r = i & 127;
        const int pf = row0 + r;
        const int b  = pf / SP;
        const int p  = pf - b * SP;
        out[((size_t)b * CDIM + c0 + c) * SP + p] = sT[c * 132 + r] + bout[c0 + c];
    }
}

// ---------------------------------------------------------------------------
extern "C" void kernel_launch(void* const* d_in, const int* in_sizes, int n_in,
                              void* d_out, int out_size)
{
    const float* x    = (const float*)d_in[0];
    const float* Wk   = (const float*)d_in[2];
    const float* Wv   = (const float*)d_in[3];
    const float* Wq   = (const float*)d_in[4];
    const float* Wout = (const float*)d_in[5];
    const float* bout = (const float*)d_in[6];
    float* out = (float*)d_out;

    cudaFuncSetAttribute(proj_mma_kernel, cudaFuncAttributeMaxDynamicSharedMemorySize,
                         PROJ_SMEM_HALVES * 2);
    cudaFuncSetAttribute(attn_kernel, cudaFuncAttributeMaxDynamicSharedMemorySize,
                         ATTN_SMEM_BYTES);
    cudaFuncSetAttribute(outproj_mma_kernel, cudaFuncAttributeMaxDynamicSharedMemorySize,
                         OUTP_SMEM_BYTES);

    convertX_kernel<<<dim3(SP / 64, CDIM / 64, BATCH), 256>>>(x);
    convertW_kernel<<<256, 256>>>(Wk, Wv, Wq, Wout);
    proj_mma_kernel<<<dim3(NPOS / 128, CDIM / 64), 256, PROJ_SMEM_HALVES * 2>>>();
    attn_kernel<<<dim3(NWIN, 2), 128, ATTN_SMEM_BYTES>>>();
    outproj_mma_kernel<<<dim3(NPOS / 128, CDIM / 64), 256, OUTP_SMEM_BYTES>>>(bout, out);
}

// round 6
// speedup vs baseline: 1.8802x; 1.1795x over previous
#include <cuda_runtime.h>
#include <cuda_bf16.h>
#include <stdint.h>

#define BATCH 4
#define CDIM  256
#define HH    120
#define WWID  120
#define SP    (HH*WWID)
#define NB    24
#define NWIN  (BATCH*NB*NB)       // 2304
#define NPOS  (BATCH*SP)          // 57600
#define QSCALE 0.17677669529663688f

#define NEGW  (-0.5f)
#define POSW  (4.0f/3.0f)
#define NORW  (-0.375f)
#define CNORW (4.0f)
#define PW    (1.8333333333333333f)   // POSW - NEGW
#define C0W   (4.375f)                // CNORW - NORW

// fp32 projections (read by attn)
__device__ float g_xk[NPOS*CDIM];
__device__ float g_xv[NPOS*CDIM];
__device__ float g_xq[NPOS*CDIM];
// bf16 split inputs for MMA
__device__ __nv_bfloat16 g_xh[NPOS*CDIM];
__device__ __nv_bfloat16 g_xl[NPOS*CDIM];
__device__ __nv_bfloat16 g_yh[NPOS*CDIM];
__device__ __nv_bfloat16 g_yl[NPOS*CDIM];
__device__ __nv_bfloat16 g_wh[4*CDIM*CDIM];   // Wk,Wv,Wq,Wout
__device__ __nv_bfloat16 g_wl[4*CDIM*CDIM];

__device__ __forceinline__ uint32_t sptr(const void* p) {
    return (uint32_t)__cvta_generic_to_shared(p);
}

#define LDM_X4(R, A) asm volatile( \
    "ldmatrix.sync.aligned.m8n8.x4.shared.b16 {%0,%1,%2,%3}, [%4];" \
    : "=r"((R)[0]), "=r"((R)[1]), "=r"((R)[2]), "=r"((R)[3]) : "r"(A))

#define MMA_BF16(D, A, B0, B1) asm volatile( \
    "mma.sync.aligned.m16n8k16.row.col.f32.bf16.bf16.f32 " \
    "{%0,%1,%2,%3},{%4,%5,%6,%7},{%8,%9},{%0,%1,%2,%3};" \
    : "+f"((D)[0]), "+f"((D)[1]), "+f"((D)[2]), "+f"((D)[3]) \
    : "r"((A)[0]), "r"((A)[1]), "r"((A)[2]), "r"((A)[3]), "r"(B0), "r"(B1))

#define CP_ASYNC16(dst, src) asm volatile( \
    "cp.async.cg.shared.global [%0], [%1], 16;" :: "r"(dst), "l"(src))
#define CP_COMMIT() asm volatile("cp.async.commit_group;")
#define CP_WAIT1()  asm volatile("cp.async.wait_group 1;")
#define CP_WAIT0()  asm volatile("cp.async.wait_group 0;")

// ---------------------------------------------------------------------------
// Convert x [b][k][p] fp32 -> g_xh/g_xl [b*SP + p][k] bf16 hi/lo (transpose)
// ---------------------------------------------------------------------------
__global__ __launch_bounds__(256) void convertX_kernel(const float* __restrict__ x)
{
    __shared__ float st[64][65];
    const int p0 = blockIdx.x * 64;
    const int k0 = blockIdx.y * 64;
    const int b  = blockIdx.z;
    const int t  = threadIdx.x;

    for (int idx = t; idx < 4096; idx += 256) {
        const int k = idx >> 6, p = idx & 63;
        st[k][p] = x[((size_t)b * CDIM + k0 + k) * SP + p0 + p];
    }
    __syncthreads();
    for (int idx = t; idx < 2048; idx += 256) {
        const int p = idx >> 5, kk = idx & 31, k = kk * 2;
        const float v0 = st[k][p], v1 = st[k + 1][p];
        const __nv_bfloat16 h0 = __float2bfloat16(v0);
        const __nv_bfloat16 h1 = __float2bfloat16(v1);
        const __nv_bfloat16 l0 = __float2bfloat16(v0 - __bfloat162float(h0));
        const __nv_bfloat16 l1 = __float2bfloat16(v1 - __bfloat162float(h1));
        const size_t o = ((size_t)b * SP + p0 + p) * CDIM + k0 + k;
        *(__nv_bfloat162*)&g_xh[o] = __halves2bfloat162(h0, h1);
        *(__nv_bfloat162*)&g_xl[o] = __halves2bfloat162(l0, l1);
    }
}

__global__ __launch_bounds__(256) void convertW_kernel(
    const float* __restrict__ Wk, const float* __restrict__ Wv,
    const float* __restrict__ Wq, const float* __restrict__ Wout)
{
    const int i = blockIdx.x * 256 + threadIdx.x;   // 0..65535
    const float* srcs[4] = {Wk, Wv, Wq, Wout};
#pragma unroll
    for (int m = 0; m < 4; m++) {
        const float v = srcs[m][i];
        const __nv_bfloat16 h = __float2bfloat16(v);
        g_wh[m * 65536 + i] = h;
        g_wl[m * 65536 + i] = __float2bfloat16(v - __bfloat162float(h));
    }
}

// ---------------------------------------------------------------------------
// proj3 via mma.sync, cp.async double-buffered.  KC=32, 8 chunks.
// Stage layout (bytes): Ah[128x80]=10240, Al=10240, Bh[3x64x80]=15360, Bl=15360.
// ---------------------------------------------------------------------------
#define PJ_STAGE 51200
#define PJ_SMEM  (2*PJ_STAGE)      // 102400

__device__ __forceinline__ void pj_load_chunk(char* base, int t, int row0, int c0,
                                              int chunk)
{
    const int kc = chunk * 32;
    for (int i = t; i < 1024; i += 256) {
        const int half = i >> 9, r = (i >> 2) & 127, seg = i & 3;
        const __nv_bfloat16* src = (half ? g_xl : g_xh)
            + (size_t)(row0 + r) * CDIM + kc + seg * 8;
        CP_ASYNC16(sptr(base + half * 10240 + r * 80 + seg * 16), src);
    }
    for (int i = t; i < 1536; i += 256) {
        const int half = (i >= 768), rem = i - half * 768;
        const int pr = rem >> 8, rr = (rem >> 2) & 63, seg = rem & 3;
        const __nv_bfloat16* src = (half ? g_wl : g_wh)
            + (size_t)pr * 65536 + (size_t)(c0 + rr) * CDIM + kc + seg * 8;
        CP_ASYNC16(sptr(base + 20480 + half * 15360 + pr * 5120 + rr * 80 + seg * 16),
                   src);
    }
}

__global__ __launch_bounds__(256, 2) void proj_mma_kernel()
{
    extern __shared__ char smem[];
    const int t = threadIdx.x;
    const int warp = t >> 5, lane = t & 31;
    const int wm = warp >> 1, wn = warp & 1;
    const int row0 = blockIdx.x * 128;
    const int c0   = blockIdx.y * 64;

    float acc[3][2][4][4];
#pragma unroll
    for (int a = 0; a < 3; a++)
#pragma unroll
        for (int b = 0; b < 2; b++)
#pragma unroll
            for (int c = 0; c < 4; c++)
#pragma unroll
                for (int d = 0; d < 4; d++) acc[a][b][c][d] = 0.f;

    pj_load_chunk(smem, t, row0, c0, 0);
    CP_COMMIT();

    for (int ch = 0; ch < 8; ch++) {
        if (ch < 7) {
            pj_load_chunk(smem + ((ch + 1) & 1) * PJ_STAGE, t, row0, c0, ch + 1);
            CP_COMMIT();
            CP_WAIT1();
        } else {
            CP_WAIT0();
        }
        __syncthreads();
        char* base = smem + (ch & 1) * PJ_STAGE;

#pragma unroll
        for (int ks = 0; ks < 2; ks++) {
            uint32_t Ah[2][4], Al[2][4];
            const int colb = ks * 32 + ((lane >> 4) << 4);   // byte col offset
#pragma unroll
            for (int mt = 0; mt < 2; mt++) {
                const int r = wm * 32 + mt * 16 + (lane & 15);
                LDM_X4(Ah[mt], sptr(base + r * 80 + colb));
                LDM_X4(Al[mt], sptr(base + 10240 + r * 80 + colb));
            }
#pragma unroll
            for (int pr = 0; pr < 3; pr++) {
#pragma unroll
                for (int pair = 0; pair < 2; pair++) {
                    const int nr = wn * 32 + pair * 16 + (lane & 15);
                    uint32_t bh[4], bl[4];
                    LDM_X4(bh, sptr(base + 20480 + pr * 5120 + nr * 80 + colb));
                    LDM_X4(bl, sptr(base + 35840 + pr * 5120 + nr * 80 + colb));
#pragma unroll
                    for (int mt = 0; mt < 2; mt++) {
#pragma unroll
                        for (int sub = 0; sub < 2; sub++) {
                            const int nt = pair * 2 + sub;
                            MMA_BF16(acc[pr][mt][nt], Ah[mt], bh[sub], bh[sub + 2]);
                            MMA_BF16(acc[pr][mt][nt], Ah[mt], bl[sub], bl[sub + 2]);
                            MMA_BF16(acc[pr][mt][nt], Al[mt], bh[sub], bh[sub + 2]);
                        }
                    }
                }
            }
        }
        __syncthreads();
    }

    const int rbase = row0 + wm * 32 + (lane >> 2);
    const int cbase = c0 + wn * 32 + (lane & 3) * 2;
    float* dsts[3] = {g_xk, g_xv, g_xq};
#pragma unroll
    for (int pr = 0; pr < 3; pr++) {
        const float s = (pr == 2) ? QSCALE : 1.f;
#pragma unroll
        for (int mt = 0; mt < 2; mt++) {
#pragma unroll
            for (int nt = 0; nt < 4; nt++) {
                const int r = rbase + mt * 16;
                const int c = cbase + nt * 8;
                float* d = dsts[pr];
                *(float2*)&d[(size_t)r * CDIM + c] =
                    make_float2(acc[pr][mt][nt][0] * s, acc[pr][mt][nt][1] * s);
                *(float2*)&d[(size_t)(r + 8) * CDIM + c] =
                    make_float2(acc[pr][mt][nt][2] * s, acc[pr][mt][nt][3] * s);
            }
        }
    }
}

// ---------------------------------------------------------------------------
// attn: CTA = (window, head-half). 128 threads; t<100 compute (4 heads x 25 q).
// Sparse-template algebra: tw_i = NEGW*ones + PW*(3-tap), t0 = NORW*ones + C0W*c.
// ---------------------------------------------------------------------------
#define ATTN_SMEM_BYTES (2 * 4 * 49 * 36 * 4)
__global__ __launch_bounds__(128) void attn_kernel()
{
    extern __shared__ float sm_att[];
    float* sK = sm_att;
    float* sV = sm_att + 4 * 49 * 36;

    const int blk  = blockIdx.x;
    const int half = blockIdx.y;
    const int b    = blk / (NB * NB);
    const int wrem = blk % (NB * NB);
    const int wy = wrem / NB, wx = wrem % NB;
    const int t = threadIdx.x;
    const int c0 = half * 128;

    const int ky0 = wy * 5 - 1, kx0 = wx * 5 - 1;
    for (int idx = t; idx < 49 * 32; idx += 128) {
        const int r  = idx >> 5;
        const int c4 = idx & 31;
        const int y  = ky0 + r / 7;
        const int xx = kx0 + r % 7;
        float4 vk = make_float4(0.f, 0.f, 0.f, 0.f);
        float4 vv = make_float4(0.f, 0.f, 0.f, 0.f);
        if (y >= 0 && y < HH && xx >= 0 && xx < WWID) {
            const size_t g = ((size_t)b * SP + y * WWID + xx) * CDIM + c0 + c4 * 4;
            vk = *(const float4*)&g_xk[g];
            vv = *(const float4*)&g_xv[g];
        }
        const int f = c4 * 4, hl = f >> 5, cc = f & 31;
        *(float4*)&sK[(hl * 49 + r) * 36 + cc] = vk;
        *(float4*)&sV[(hl * 49 + r) * 36 + cc] = vv;
    }
    __syncthreads();

    if (t < 100) {
        const int hl = t / 25, q = t % 25;
        const int hg = half * 4 + hl;
        const int qy = q / 5, qx = q % 5;
        const size_t qpos = ((size_t)b * SP + (wy * 5 + qy) * WWID + wx * 5 + qx) * CDIM
                            + hg * 32;

        float qv[32];
#pragma unroll
        for (int c4 = 0; c4 < 8; c4++) {
            const float4 v = *(const float4*)&g_xq[qpos + c4 * 4];
            qv[c4*4+0] = v.x; qv[c4*4+1] = v.y; qv[c4*4+2] = v.z; qv[c4*4+3] = v.w;
        }

        float S[49];
#pragma unroll
        for (int p = 0; p < 49; p++) {
            float a0 = 0.f;
#pragma unroll
            for (int c4 = 0; c4 < 8; c4++) {
                const float4 kv = *(const float4*)&sK[(hl * 49 + p) * 36 + c4 * 4];
                a0 += qv[c4*4+0]*kv.x + qv[c4*4+1]*kv.y + qv[c4*4+2]*kv.z + qv[c4*4+3]*kv.w;
            }
            S[p] = a0;
        }

        float mpos = S[0], mneg = S[0];
#pragma unroll
        for (int p = 1; p < 49; p++) { mpos = fmaxf(mpos, S[p]); mneg = fminf(mneg, S[p]); }
        const float m = 4.0f * mpos - 3.0f * mneg;

        float Ar[49];
#pragma unroll
        for (int p = 0; p < 49; p++) Ar[p] = 0.f;

        float ssum = 0.f;
#pragma unroll
        for (int ky = 0; ky < 5; ky++) {
#pragma unroll
            for (int kx = 0; kx < 5; kx++) {
                const float c  = S[(ky+1)*7 + kx+1];
                const float u  = S[(ky  )*7 + kx+1];
                const float d  = S[(ky+2)*7 + kx+1];
                const float l  = S[(ky+1)*7 + kx  ];
                const float r  = S[(ky+1)*7 + kx+2];
                const float tl = S[(ky  )*7 + kx  ];
                const float tr = S[(ky  )*7 + kx+2];
                const float bl = S[(ky+2)*7 + kx  ];
                const float br = S[(ky+2)*7 + kx+2];
                const float s_ud = u + d, s_lr = l + r;
                const float dg = tl + br, ad = tr + bl;
                const float sum9 = ((s_ud + s_lr) + (dg + ad)) + c;
                const float base = fmaf(NEGW, sum9, -m);
                const float e0 = __expf(fmaf(NORW, sum9, fmaf(C0W, c, -m)));
                const float e1 = __expf(fmaf(PW, s_ud + c, base));
                const float e2 = __expf(fmaf(PW, s_lr + c, base));
                const float e3 = __expf(fmaf(PW, dg + c, base));
                const float e4 = __expf(fmaf(PW, ad + c, base));
                const float e5 = __expf(fmaf(PW, (u + l) + c, base));
                const float e6 = __expf(fmaf(PW, (u + r) + c, base));
                const float e7 = __expf(fmaf(PW, (l + d) + c, base));
                const float e8 = __expf(fmaf(PW, (r + d) + c, base));
                const float E = ((e1 + e2) + (e3 + e4)) + ((e5 + e6) + (e7 + e8));
                ssum += E + e0;
                const float basea = fmaf(NEGW, E, NORW * e0);
                Ar[(ky  )*7 + kx  ] += fmaf(PW, e3, basea);
                Ar[(ky  )*7 + kx+1] += fmaf(PW, (e1 + e5) + e6, basea);
                Ar[(ky  )*7 + kx+2] += fmaf(PW, e4, basea);
                Ar[(ky+1)*7 + kx  ] += fmaf(PW, (e2 + e5) + e7, basea);
                Ar[(ky+1)*7 + kx+1] += fmaf(PW, E, fmaf(C0W, e0, basea));
                Ar[(ky+1)*7 + kx+2] += fmaf(PW, (e2 + e6) + e8, basea);
                Ar[(ky+2)*7 + kx  ] += fmaf(PW, e4, basea);
                Ar[(ky+2)*7 + kx+1] += fmaf(PW, (e1 + e7) + e8, basea);
                Ar[(ky+2)*7 + kx+2] += fmaf(PW, e3, basea);
            }
        }

        const float inv = 1.0f / ssum;
        float o[32];
#pragma unroll
        for (int c = 0; c < 32; c++) o[c] = 0.f;
#pragma unroll
        for (int p = 0; p < 49; p++) {
            const float a = Ar[p];
#pragma unroll
            for (int c4 = 0; c4 < 8; c4++) {
                const float4 vv = *(const float4*)&sV[(hl * 49 + p) * 36 + c4 * 4];
                o[c4*4+0] += a * vv.x; o[c4*4+1] += a * vv.y;
                o[c4*4+2] += a * vv.z; o[c4*4+3] += a * vv.w;
            }
        }

#pragma unroll
        for (int j = 0; j < 16; j++) {
            const float v0 = o[2*j]   * inv;
            const float v1 = o[2*j+1] * inv;
            const __nv_bfloat16 h0 = __float2bfloat16(v0);
            const __nv_bfloat16 h1 = __float2bfloat16(v1);
            const __nv_bfloat16 l0 = __float2bfloat16(v0 - __bfloat162float(h0));
            const __nv_bfloat16 l1 = __float2bfloat16(v1 - __bfloat162float(h1));
            *(__nv_bfloat162*)&g_yh[qpos + 2*j] = __halves2bfloat162(h0, h1);
            *(__nv_bfloat162*)&g_yl[qpos + 2*j] = __halves2bfloat162(l0, l1);
        }
    }
}

// ---------------------------------------------------------------------------
// outproj via mma.sync, cp.async double-buffered.  KC=32, 8 chunks.
// Stage: Ah 10240 + Al 10240 + Bh 5120 + Bl 5120 = 30720.  sT overlays stage0.
// ---------------------------------------------------------------------------
#define OP_STAGE 30720
#define OP_BIAS  (2*OP_STAGE)              // 61440, 256B bias
#define OP_SMEM  (2*OP_STAGE + 256)

__device__ __forceinline__ void op_load_chunk(char* base, int t, int row0, int c0,
                                              int chunk)
{
    const int kc = chunk * 32;
    for (int i = t; i < 1024; i += 256) {
        const int half = i >> 9, r = (i >> 2) & 127, seg = i & 3;
        const __nv_bfloat16* src = (half ? g_yl : g_yh)
            + (size_t)(row0 + r) * CDIM + kc + seg * 8;
        CP_ASYNC16(sptr(base + half * 10240 + r * 80 + seg * 16), src);
    }
    for (int i = t; i < 512; i += 256) {
        const int half = i >> 8, rr = (i >> 2) & 63, seg = i & 3;
        const __nv_bfloat16* src = (half ? g_wl : g_wh)
            + (size_t)3 * 65536 + (size_t)(c0 + rr) * CDIM + kc + seg * 8;
        CP_ASYNC16(sptr(base + 20480 + half * 5120 + rr * 80 + seg * 16), src);
    }
}

__global__ __launch_bounds__(256, 2) void outproj_mma_kernel(
    const float* __restrict__ bout, float* __restrict__ out)
{
    extern __shared__ char smem[];
    float* sT = (float*)smem;
    float* sBias = (float*)(smem + OP_BIAS);
    const int t = threadIdx.x;
    const int warp = t >> 5, lane = t & 31;
    const int wm = warp >> 1, wn = warp & 1;
    const int row0 = blockIdx.x * 128;
    const int c0   = blockIdx.y * 64;

    if (t < 64) sBias[t] = bout[c0 + t];

    float acc[2][4][4];
#pragma unroll
    for (int b = 0; b < 2; b++)
#pragma unroll
        for (int c = 0; c < 4; c++)
#pragma unroll
            for (int d = 0; d < 4; d++) acc[b][c][d] = 0.f;

    op_load_chunk(smem, t, row0, c0, 0);
    CP_COMMIT();

    for (int ch = 0; ch < 8; ch++) {
        if (ch < 7) {
            op_load_chunk(smem + ((ch + 1) & 1) * OP_STAGE, t, row0, c0, ch + 1);
            CP_COMMIT();
            CP_WAIT1();
        } else {
            CP_WAIT0();
        }
        __syncthreads();
        char* base = smem + (ch & 1) * OP_STAGE;

#pragma unroll
        for (int ks = 0; ks < 2; ks++) {
            uint32_t Ah[2][4], Al[2][4];
            const int colb = ks * 32 + ((lane >> 4) << 4);
#pragma unroll
            for (int mt = 0; mt < 2; mt++) {
                const int r = wm * 32 + mt * 16 + (lane & 15);
                LDM_X4(Ah[mt], sptr(base + r * 80 + colb));
                LDM_X4(Al[mt], sptr(base + 10240 + r * 80 + colb));
            }
#pragma unroll
            for (int pair = 0; pair < 2; pair++) {
                const int nr = wn * 32 + pair * 16 + (lane & 15);
                uint32_t bh[4], bl[4];
                LDM_X4(bh, sptr(base + 20480 + nr * 80 + colb));
                LDM_X4(bl, sptr(base + 25600 + nr * 80 + colb));
#pragma unroll
                for (int mt = 0; mt < 2; mt++) {
#pragma unroll
                    for (int sub = 0; sub < 2; sub++) {
                        const int nt = pair * 2 + sub;
                        MMA_BF16(acc[mt][nt], Ah[mt], bh[sub], bh[sub + 2]);
                        MMA_BF16(acc[mt][nt], Ah[mt], bl[sub], bl[sub + 2]);
                        MMA_BF16(acc[mt][nt], Al[mt], bh[sub], bh[sub + 2]);
                    }
                }
            }
        }
        __syncthreads();
    }

    // epilogue: transpose via smem (overlays stage buffers) to NCHW
    const int rl = wm * 32 + (lane >> 2);
    const int cl = wn * 32 + (lane & 3) * 2;
#pragma unroll
    for (int mt = 0; mt < 2; mt++) {
#pragma unroll
        for (int nt = 0; nt < 4; nt++) {
            const int r = rl + mt * 16;
            const int c = cl + nt * 8;
            sT[(c    ) * 132 + r    ] = acc[mt][nt][0];
            sT[(c + 1) * 132 + r    ] = acc[mt][nt][1];
            sT[(c    ) * 132 + r + 8] = acc[mt][nt][2];
            sT[(c + 1) * 132 + r + 8] = acc[mt][nt][3];
        }
    }
    __syncthreads();

    for (int i = t; i < 8192; i += 256) {
        const int c = i >> 7, r = i & 127;
        const int pf = row0 + r;
        const int b  = pf / SP;
        const int p  = pf - b * SP;
        out[((size_t)b * CDIM + c0 + c) * SP + p] = sT[c * 132 + r] + sBias[c];
    }
}

// ---------------------------------------------------------------------------
extern "C" void kernel_launch(void* const* d_in, const int* in_sizes, int n_in,
                              void* d_out, int out_size)
{
    const float* x    = (const float*)d_in[0];
    const float* Wk   = (const float*)d_in[2];
    const float* Wv   = (const float*)d_in[3];
    const float* Wq   = (const float*)d_in[4];
    const float* Wout = (const float*)d_in[5];
    const float* bout = (const float*)d_in[6];
    float* out = (float*)d_out;

    cudaFuncSetAttribute(proj_mma_kernel, cudaFuncAttributeMaxDynamicSharedMemorySize,
                         PJ_SMEM);
    cudaFuncSetAttribute(attn_kernel, cudaFuncAttributeMaxDynamicSharedMemorySize,
                         ATTN_SMEM_BYTES);
    cudaFuncSetAttribute(outproj_mma_kernel, cudaFuncAttributeMaxDynamicSharedMemorySize,
                         OP_SMEM);

    convertX_kernel<<<dim3(SP / 64, CDIM / 64, BATCH), 256>>>(x);
    convertW_kernel<<<256, 256>>>(Wk, Wv, Wq, Wout);
    proj_mma_kernel<<<dim3(NPOS / 128, CDIM / 64), 256, PJ_SMEM>>>();
    attn_kernel<<<dim3(NWIN, 2), 128, ATTN_SMEM_BYTES>>>();
    outproj_mma_kernel<<<dim3(NPOS / 128, CDIM / 64), 256, OP_SMEM>>>(bout, out);
}

// round 7
// speedup vs baseline: 1.9065x; 1.0140x over previous
#include <cuda_runtime.h>
#include <cuda_bf16.h>
#include <stdint.h>

#define BATCH 4
#define CDIM  256
#define HH    120
#define WWID  120
#define SP    (HH*WWID)
#define NB    24
#define NWIN  (BATCH*NB*NB)       // 2304
#define NPOS  (BATCH*SP)          // 57600
#define QSCALE 0.17677669529663688f

#define NEGW  (-0.5f)
#define POSW  (4.0f/3.0f)
#define NORW  (-0.375f)
#define CNORW (4.0f)
#define PW    (1.8333333333333333f)   // POSW - NEGW
#define C0W   (4.375f)                // CNORW - NORW

// fp32 projections (read by attn)
__device__ float g_xk[NPOS*CDIM];
__device__ float g_xv[NPOS*CDIM];
__device__ float g_xq[NPOS*CDIM];
// bf16 split inputs for MMA
__device__ __nv_bfloat16 g_xh[NPOS*CDIM];
__device__ __nv_bfloat16 g_xl[NPOS*CDIM];
__device__ __nv_bfloat16 g_yh[NPOS*CDIM];
__device__ __nv_bfloat16 g_yl[NPOS*CDIM];
__device__ __nv_bfloat16 g_wh[4*CDIM*CDIM];   // Wk,Wv,Wq,Wout
__device__ __nv_bfloat16 g_wl[4*CDIM*CDIM];

__device__ __forceinline__ uint32_t sptr(const void* p) {
    return (uint32_t)__cvta_generic_to_shared(p);
}

#define LDM_X4(R, A) asm volatile( \
    "ldmatrix.sync.aligned.m8n8.x4.shared.b16 {%0,%1,%2,%3}, [%4];" \
    : "=r"((R)[0]), "=r"((R)[1]), "=r"((R)[2]), "=r"((R)[3]) : "r"(A))

#define MMA_BF16(D, A, B0, B1) asm volatile( \
    "mma.sync.aligned.m16n8k16.row.col.f32.bf16.bf16.f32 " \
    "{%0,%1,%2,%3},{%4,%5,%6,%7},{%8,%9},{%0,%1,%2,%3};" \
    : "+f"((D)[0]), "+f"((D)[1]), "+f"((D)[2]), "+f"((D)[3]) \
    : "r"((A)[0]), "r"((A)[1]), "r"((A)[2]), "r"((A)[3]), "r"(B0), "r"(B1))

#define CP_ASYNC16(dst, src) asm volatile( \
    "cp.async.cg.shared.global [%0], [%1], 16;" :: "r"(dst), "l"(src))
#define CP_COMMIT() asm volatile("cp.async.commit_group;")
#define CP_WAIT1()  asm volatile("cp.async.wait_group 1;")
#define CP_WAIT0()  asm volatile("cp.async.wait_group 0;")

// ---- packed f32x2 (Blackwell sm_100+) ----
#define FMA2(d, a, b) asm("fma.rn.f32x2 %0, %1, %2, %0;" : "+l"(d) : "l"(a), "l"(b))
#define ADD2(d, a, b) asm("add.rn.f32x2 %0, %1, %2;" : "=l"(d) : "l"(a), "l"(b))
#define PACK2(d, s)   asm("mov.b64 %0, {%1, %1};" : "=l"(d) : "r"(s))
#define UNPACK2(lo, hi, v) asm("mov.b64 {%0, %1}, %2;" : "=r"(lo), "=r"(hi) : "l"(v))

// ---------------------------------------------------------------------------
// Convert x [b][k][p] fp32 -> g_xh/g_xl [b*SP + p][k] bf16 hi/lo (transpose)
// ---------------------------------------------------------------------------
__global__ __launch_bounds__(256) void convertX_kernel(const float* __restrict__ x)
{
    __shared__ float st[64][65];
    const int p0 = blockIdx.x * 64;
    const int k0 = blockIdx.y * 64;
    const int b  = blockIdx.z;
    const int t  = threadIdx.x;

    for (int idx = t; idx < 4096; idx += 256) {
        const int k = idx >> 6, p = idx & 63;
        st[k][p] = x[((size_t)b * CDIM + k0 + k) * SP + p0 + p];
    }
    __syncthreads();
    for (int idx = t; idx < 2048; idx += 256) {
        const int p = idx >> 5, kk = idx & 31, k = kk * 2;
        const float v0 = st[k][p], v1 = st[k + 1][p];
        const __nv_bfloat16 h0 = __float2bfloat16(v0);
        const __nv_bfloat16 h1 = __float2bfloat16(v1);
        const __nv_bfloat16 l0 = __float2bfloat16(v0 - __bfloat162float(h0));
        const __nv_bfloat16 l1 = __float2bfloat16(v1 - __bfloat162float(h1));
        const size_t o = ((size_t)b * SP + p0 + p) * CDIM + k0 + k;
        *(__nv_bfloat162*)&g_xh[o] = __halves2bfloat162(h0, h1);
        *(__nv_bfloat162*)&g_xl[o] = __halves2bfloat162(l0, l1);
    }
}

__global__ __launch_bounds__(256) void convertW_kernel(
    const float* __restrict__ Wk, const float* __restrict__ Wv,
    const float* __restrict__ Wq, const float* __restrict__ Wout)
{
    const int i = blockIdx.x * 256 + threadIdx.x;   // 0..65535
    const float* srcs[4] = {Wk, Wv, Wq, Wout};
#pragma unroll
    for (int m = 0; m < 4; m++) {
        const float v = srcs[m][i];
        const __nv_bfloat16 h = __float2bfloat16(v);
        g_wh[m * 65536 + i] = h;
        g_wl[m * 65536 + i] = __float2bfloat16(v - __bfloat162float(h));
    }
}

// ---------------------------------------------------------------------------
// proj3 via mma.sync, cp.async double-buffered.  KC=32, 8 chunks.
// ---------------------------------------------------------------------------
#define PJ_STAGE 51200
#define PJ_SMEM  (2*PJ_STAGE)      // 102400

__device__ __forceinline__ void pj_load_chunk(char* base, int t, int row0, int c0,
                                              int chunk)
{
    const int kc = chunk * 32;
    for (int i = t; i < 1024; i += 256) {
        const int half = i >> 9, r = (i >> 2) & 127, seg = i & 3;
        const __nv_bfloat16* src = (half ? g_xl : g_xh)
            + (size_t)(row0 + r) * CDIM + kc + seg * 8;
        CP_ASYNC16(sptr(base + half * 10240 + r * 80 + seg * 16), src);
    }
    for (int i = t; i < 1536; i += 256) {
        const int half = (i >= 768), rem = i - half * 768;
        const int pr = rem >> 8, rr = (rem >> 2) & 63, seg = rem & 3;
        const __nv_bfloat16* src = (half ? g_wl : g_wh)
            + (size_t)pr * 65536 + (size_t)(c0 + rr) * CDIM + kc + seg * 8;
        CP_ASYNC16(sptr(base + 20480 + half * 15360 + pr * 5120 + rr * 80 + seg * 16),
                   src);
    }
}

__global__ __launch_bounds__(256, 2) void proj_mma_kernel()
{
    extern __shared__ char smem[];
    const int t = threadIdx.x;
    const int warp = t >> 5, lane = t & 31;
    const int wm = warp >> 1, wn = warp & 1;
    const int row0 = blockIdx.x * 128;
    const int c0   = blockIdx.y * 64;

    float acc[3][2][4][4];
#pragma unroll
    for (int a = 0; a < 3; a++)
#pragma unroll
        for (int b = 0; b < 2; b++)
#pragma unroll
            for (int c = 0; c < 4; c++)
#pragma unroll
                for (int d = 0; d < 4; d++) acc[a][b][c][d] = 0.f;

    pj_load_chunk(smem, t, row0, c0, 0);
    CP_COMMIT();

    for (int ch = 0; ch < 8; ch++) {
        if (ch < 7) {
            pj_load_chunk(smem + ((ch + 1) & 1) * PJ_STAGE, t, row0, c0, ch + 1);
            CP_COMMIT();
            CP_WAIT1();
        } else {
            CP_WAIT0();
        }
        __syncthreads();
        char* base = smem + (ch & 1) * PJ_STAGE;

#pragma unroll
        for (int ks = 0; ks < 2; ks++) {
            uint32_t Ah[2][4], Al[2][4];
            const int colb = ks * 32 + ((lane >> 4) << 4);
#pragma unroll
            for (int mt = 0; mt < 2; mt++) {
                const int r = wm * 32 + mt * 16 + (lane & 15);
                LDM_X4(Ah[mt], sptr(base + r * 80 + colb));
                LDM_X4(Al[mt], sptr(base + 10240 + r * 80 + colb));
            }
#pragma unroll
            for (int pr = 0; pr < 3; pr++) {
#pragma unroll
                for (int pair = 0; pair < 2; pair++) {
                    const int nr = wn * 32 + pair * 16 + (lane & 15);
                    uint32_t bh[4], bl[4];
                    LDM_X4(bh, sptr(base + 20480 + pr * 5120 + nr * 80 + colb));
                    LDM_X4(bl, sptr(base + 35840 + pr * 5120 + nr * 80 + colb));
#pragma unroll
                    for (int mt = 0; mt < 2; mt++) {
#pragma unroll
                        for (int sub = 0; sub < 2; sub++) {
                            const int nt = pair * 2 + sub;
                            MMA_BF16(acc[pr][mt][nt], Ah[mt], bh[sub], bh[sub + 2]);
                            MMA_BF16(acc[pr][mt][nt], Ah[mt], bl[sub], bl[sub + 2]);
                            MMA_BF16(acc[pr][mt][nt], Al[mt], bh[sub], bh[sub + 2]);
                        }
                    }
                }
            }
        }
        __syncthreads();
    }

    const int rbase = row0 + wm * 32 + (lane >> 2);
    const int cbase = c0 + wn * 32 + (lane & 3) * 2;
    float* dsts[3] = {g_xk, g_xv, g_xq};
#pragma unroll
    for (int pr = 0; pr < 3; pr++) {
        const float s = (pr == 2) ? QSCALE : 1.f;
#pragma unroll
        for (int mt = 0; mt < 2; mt++) {
#pragma unroll
            for (int nt = 0; nt < 4; nt++) {
                const int r = rbase + mt * 16;
                const int c = cbase + nt * 8;
                float* d = dsts[pr];
                *(float2*)&d[(size_t)r * CDIM + c] =
                    make_float2(acc[pr][mt][nt][0] * s, acc[pr][mt][nt][1] * s);
                *(float2*)&d[(size_t)(r + 8) * CDIM + c] =
                    make_float2(acc[pr][mt][nt][2] * s, acc[pr][mt][nt][3] * s);
            }
        }
    }
}

// ---------------------------------------------------------------------------
// attn: CTA = (window, head-half). 128 threads; t<100 compute (4 heads x 25 q).
// f32x2 packed math for S and AV; streaming 3-row Ar window fused with AV.
// ---------------------------------------------------------------------------
#define ATTN_SMEM_BYTES (2 * 4 * 49 * 36 * 4)
__global__ __launch_bounds__(128) void attn_kernel()
{
    extern __shared__ float sm_att[];
    float* sK = sm_att;
    float* sV = sm_att + 4 * 49 * 36;

    const int blk  = blockIdx.x;
    const int half = blockIdx.y;
    const int b    = blk / (NB * NB);
    const int wrem = blk % (NB * NB);
    const int wy = wrem / NB, wx = wrem % NB;
    const int t = threadIdx.x;
    const int c0 = half * 128;

    const int ky0 = wy * 5 - 1, kx0 = wx * 5 - 1;
    for (int idx = t; idx < 49 * 32; idx += 128) {
        const int r  = idx >> 5;
        const int c4 = idx & 31;
        const int y  = ky0 + r / 7;
        const int xx = kx0 + r % 7;
        float4 vk = make_float4(0.f, 0.f, 0.f, 0.f);
        float4 vv = make_float4(0.f, 0.f, 0.f, 0.f);
        if (y >= 0 && y < HH && xx >= 0 && xx < WWID) {
            const size_t g = ((size_t)b * SP + y * WWID + xx) * CDIM + c0 + c4 * 4;
            vk = *(const float4*)&g_xk[g];
            vv = *(const float4*)&g_xv[g];
        }
        const int f = c4 * 4, hl = f >> 5, cc = f & 31;
        *(float4*)&sK[(hl * 49 + r) * 36 + cc] = vk;
        *(float4*)&sV[(hl * 49 + r) * 36 + cc] = vv;
    }
    __syncthreads();

    if (t < 100) {
        const int hl = t / 25, q = t % 25;
        const int qy = q / 5, qx = q % 5;
        const size_t qpos = ((size_t)b * SP + (wy * 5 + qy) * WWID + wx * 5 + qx) * CDIM
                            + (half * 4 + hl) * 32;

        // Q as 16 packed f32x2
        unsigned long long qp[16];
#pragma unroll
        for (int j = 0; j < 8; j++) {
            const ulonglong2 v = *(const ulonglong2*)&g_xq[qpos + j * 4];
            qp[2*j] = v.x; qp[2*j+1] = v.y;
        }

        // S[p] = Q . K_p  (packed)
        float S[49];
#pragma unroll
        for (int p = 0; p < 49; p++) {
            const float* kr = &sK[(hl * 49 + p) * 36];
            unsigned long long a0 = 0ull, a1 = 0ull;
#pragma unroll
            for (int j = 0; j < 8; j++) {
                const ulonglong2 kv = *(const ulonglong2*)&kr[j * 4];
                FMA2(a0, qp[2*j],   kv.x);
                FMA2(a1, qp[2*j+1], kv.y);
            }
            unsigned long long asum; ADD2(asum, a0, a1);
            uint32_t lo, hi; UNPACK2(lo, hi, asum);
            S[p] = __uint_as_float(lo) + __uint_as_float(hi);
        }

        float mpos = S[0], mneg = S[0];
#pragma unroll
        for (int p = 1; p < 49; p++) { mpos = fmaxf(mpos, S[p]); mneg = fminf(mneg, S[p]); }
        const float m = 4.0f * mpos - 3.0f * mneg;

        // streaming 3-row Ar window + fused AV (packed o accumulators)
        unsigned long long o2[16];
#pragma unroll
        for (int j = 0; j < 16; j++) o2[j] = 0ull;
        float A0[7], A1[7], A2[7];
#pragma unroll
        for (int j = 0; j < 7; j++) { A0[j] = 0.f; A1[j] = 0.f; A2[j] = 0.f; }

        float ssum = 0.f;
#pragma unroll
        for (int ky = 0; ky < 5; ky++) {
#pragma unroll
            for (int kx = 0; kx < 5; kx++) {
                const float c  = S[(ky+1)*7 + kx+1];
                const float u  = S[(ky  )*7 + kx+1];
                const float d  = S[(ky+2)*7 + kx+1];
                const float l  = S[(ky+1)*7 + kx  ];
                const float r  = S[(ky+1)*7 + kx+2];
                const float tl = S[(ky  )*7 + kx  ];
                const float tr = S[(ky  )*7 + kx+2];
                const float bl = S[(ky+2)*7 + kx  ];
                const float br = S[(ky+2)*7 + kx+2];
                const float s_ud = u + d, s_lr = l + r;
                const float dg = tl + br, ad = tr + bl;
                const float sum9 = ((s_ud + s_lr) + (dg + ad)) + c;
                const float base = fmaf(NEGW, sum9, -m);
                const float e0 = __expf(fmaf(NORW, sum9, fmaf(C0W, c, -m)));
                const float e1 = __expf(fmaf(PW, s_ud + c, base));
                const float e2 = __expf(fmaf(PW, s_lr + c, base));
                const float e3 = __expf(fmaf(PW, dg + c, base));
                const float e4 = __expf(fmaf(PW, ad + c, base));
                const float e5 = __expf(fmaf(PW, (u + l) + c, base));
                const float e6 = __expf(fmaf(PW, (u + r) + c, base));
                const float e7 = __expf(fmaf(PW, (l + d) + c, base));
                const float e8 = __expf(fmaf(PW, (r + d) + c, base));
                const float E = ((e1 + e2) + (e3 + e4)) + ((e5 + e6) + (e7 + e8));
                ssum += E + e0;
                const float basea = fmaf(NEGW, E, NORW * e0);
                A0[kx  ] += fmaf(PW, e3, basea);
                A0[kx+1] += fmaf(PW, (e1 + e5) + e6, basea);
                A0[kx+2] += fmaf(PW, e4, basea);
                A1[kx  ] += fmaf(PW, (e2 + e5) + e7, basea);
                A1[kx+1] += fmaf(PW, E, fmaf(C0W, e0, basea));
                A1[kx+2] += fmaf(PW, (e2 + e6) + e8, basea);
                A2[kx  ] += fmaf(PW, e4, basea);
                A2[kx+1] += fmaf(PW, (e1 + e7) + e8, basea);
                A2[kx+2] += fmaf(PW, e3, basea);
            }
            // row ky is final: fused AV
#pragma unroll
            for (int px = 0; px < 7; px++) {
                unsigned long long aa; PACK2(aa, __float_as_uint(A0[px]));
                const float* vr = &sV[(hl * 49 + ky * 7 + px) * 36];
#pragma unroll
                for (int j = 0; j < 8; j++) {
                    const ulonglong2 vv = *(const ulonglong2*)&vr[j * 4];
                    FMA2(o2[2*j],   aa, vv.x);
                    FMA2(o2[2*j+1], aa, vv.y);
                }
            }
            // rotate window
#pragma unroll
            for (int j = 0; j < 7; j++) { A0[j] = A1[j]; A1[j] = A2[j]; A2[j] = 0.f; }
        }
        // rows 5 (A0) and 6 (A1)
#pragma unroll
        for (int rr = 0; rr < 2; rr++) {
#pragma unroll
            for (int px = 0; px < 7; px++) {
                const float a = rr ? A1[px] : A0[px];
                unsigned long long aa; PACK2(aa, __float_as_uint(a));
                const float* vr = &sV[(hl * 49 + (5 + rr) * 7 + px) * 36];
#pragma unroll
                for (int j = 0; j < 8; j++) {
                    const ulonglong2 vv = *(const ulonglong2*)&vr[j * 4];
                    FMA2(o2[2*j],   aa, vv.x);
                    FMA2(o2[2*j+1], aa, vv.y);
                }
            }
        }

        const float inv = 1.0f / ssum;
#pragma unroll
        for (int j = 0; j < 16; j++) {
            uint32_t lo, hi; UNPACK2(lo, hi, o2[j]);
            const float v0 = __uint_as_float(lo) * inv;
            const float v1 = __uint_as_float(hi) * inv;
            const __nv_bfloat16 h0 = __float2bfloat16(v0);
            const __nv_bfloat16 h1 = __float2bfloat16(v1);
            const __nv_bfloat16 l0 = __float2bfloat16(v0 - __bfloat162float(h0));
            const __nv_bfloat16 l1 = __float2bfloat16(v1 - __bfloat162float(h1));
            *(__nv_bfloat162*)&g_yh[qpos + 2*j] = __halves2bfloat162(h0, h1);
            *(__nv_bfloat162*)&g_yl[qpos + 2*j] = __halves2bfloat162(l0, l1);
        }
    }
}

// ---------------------------------------------------------------------------
// outproj via mma.sync, cp.async double-buffered.  KC=32, 8 chunks.
// ---------------------------------------------------------------------------
#define OP_STAGE 30720
#define OP_BIAS  (2*OP_STAGE)              // 61440, 256B bias
#define OP_SMEM  (2*OP_STAGE + 256)

__device__ __forceinline__ void op_load_chunk(char* base, int t, int row0, int c0,
                                              int chunk)
{
    const int kc = chunk * 32;
    for (int i = t; i < 1024; i += 256) {
        const int half = i >> 9, r = (i >> 2) & 127, seg = i & 3;
        const __nv_bfloat16* src = (half ? g_yl : g_yh)
            + (size_t)(row0 + r) * CDIM + kc + seg * 8;
        CP_ASYNC16(sptr(base + half * 10240 + r * 80 + seg * 16), src);
    }
    for (int i = t; i < 512; i += 256) {
        const int half = i >> 8, rr = (i >> 2) & 63, seg = i & 3;
        const __nv_bfloat16* src = (half ? g_wl : g_wh)
            + (size_t)3 * 65536 + (size_t)(c0 + rr) * CDIM + kc + seg * 8;
        CP_ASYNC16(sptr(base + 20480 + half * 5120 + rr * 80 + seg * 16), src);
    }
}

__global__ __launch_bounds__(256, 2) void outproj_mma_kernel(
    const float* __restrict__ bout, float* __restrict__ out)
{
    extern __shared__ char smem[];
    float* sT = (float*)smem;
    float* sBias = (float*)(smem + OP_BIAS);
    const int t = threadIdx.x;
    const int warp = t >> 5, lane = t & 31;
    const int wm = warp >> 1, wn = warp & 1;
    const int row0 = blockIdx.x * 128;
    const int c0   = blockIdx.y * 64;

    if (t < 64) sBias[t] = bout[c0 + t];

    float acc[2][4][4];
#pragma unroll
    for (int b = 0; b < 2; b++)
#pragma unroll
        for (int c = 0; c < 4; c++)
#pragma unroll
            for (int d = 0; d < 4; d++) acc[b][c][d] = 0.f;

    op_load_chunk(smem, t, row0, c0, 0);
    CP_COMMIT();

    for (int ch = 0; ch < 8; ch++) {
        if (ch < 7) {
            op_load_chunk(smem + ((ch + 1) & 1) * OP_STAGE, t, row0, c0, ch + 1);
            CP_COMMIT();
            CP_WAIT1();
        } else {
            CP_WAIT0();
        }
        __syncthreads();
        char* base = smem + (ch & 1) * OP_STAGE;

#pragma unroll
        for (int ks = 0; ks < 2; ks++) {
            uint32_t Ah[2][4], Al[2][4];
            const int colb = ks * 32 + ((lane >> 4) << 4);
#pragma unroll
            for (int mt = 0; mt < 2; mt++) {
                const int r = wm * 32 + mt * 16 + (lane & 15);
                LDM_X4(Ah[mt], sptr(base + r * 80 + colb));
                LDM_X4(Al[mt], sptr(base + 10240 + r * 80 + colb));
            }
#pragma unroll
            for (int pair = 0; pair < 2; pair++) {
                const int nr = wn * 32 + pair * 16 + (lane & 15);
                uint32_t bh[4], bl[4];
                LDM_X4(bh, sptr(base + 20480 + nr * 80 + colb));
                LDM_X4(bl, sptr(base + 25600 + nr * 80 + colb));
#pragma unroll
                for (int mt = 0; mt < 2; mt++) {
#pragma unroll
                    for (int sub = 0; sub < 2; sub++) {
                        const int nt = pair * 2 + sub;
                        MMA_BF16(acc[mt][nt], Ah[mt], bh[sub], bh[sub + 2]);
                        MMA_BF16(acc[mt][nt], Ah[mt], bl[sub], bl[sub + 2]);
                        MMA_BF16(acc[mt][nt], Al[mt], bh[sub], bh[sub + 2]);
                    }
                }
            }
        }
        __syncthreads();
    }

    const int rl = wm * 32 + (lane >> 2);
    const int cl = wn * 32 + (lane & 3) * 2;
#pragma unroll
    for (int mt = 0; mt < 2; mt++) {
#pragma unroll
        for (int nt = 0; nt < 4; nt++) {
            const int r = rl + mt * 16;
            const int c = cl + nt * 8;
            sT[(c    ) * 132 + r    ] = acc[mt][nt][0];
            sT[(c + 1) * 132 + r    ] = acc[mt][nt][1];
            sT[(c    ) * 132 + r + 8] = acc[mt][nt][2];
            sT[(c + 1) * 132 + r + 8] = acc[mt][nt][3];
        }
    }
    __syncthreads();

    for (int i = t; i < 8192; i += 256) {
        const int c = i >> 7, r = i & 127;
        const int pf = row0 + r;
        const int b  = pf / SP;
        const int p  = pf - b * SP;
        out[((size_t)b * CDIM + c0 + c) * SP + p] = sT[c * 132 + r] + sBias[c];
    }
}

// ---------------------------------------------------------------------------
extern "C" void kernel_launch(void* const* d_in, const int* in_sizes, int n_in,
                              void* d_out, int out_size)
{
    const float* x    = (const float*)d_in[0];
    const float* Wk   = (const float*)d_in[2];
    const float* Wv   = (const float*)d_in[3];
    const float* Wq   = (const float*)d_in[4];
    const float* Wout = (const float*)d_in[5];
    const float* bout = (const float*)d_in[6];
    float* out = (float*)d_out;

    cudaFuncSetAttribute(proj_mma_kernel, cudaFuncAttributeMaxDynamicSharedMemorySize,
                         PJ_SMEM);
    cudaFuncSetAttribute(attn_kernel, cudaFuncAttributeMaxDynamicSharedMemorySize,
                         ATTN_SMEM_BYTES);
    cudaFuncSetAttribute(outproj_mma_kernel, cudaFuncAttributeMaxDynamicSharedMemorySize,
                         OP_SMEM);

    convertX_kernel<<<dim3(SP / 64, CDIM / 64, BATCH), 256>>>(x);
    convertW_kernel<<<256, 256>>>(Wk, Wv, Wq, Wout);
    proj_mma_kernel<<<dim3(NPOS / 128, CDIM / 64), 256, PJ_SMEM>>>();
    attn_kernel<<<dim3(NWIN, 2), 128, ATTN_SMEM_BYTES>>>();
    outproj_mma_kernel<<<dim3(NPOS / 128, CDIM / 64), 256, OP_SMEM>>>(bout, out);
}

// round 9
// speedup vs baseline: 2.1303x; 1.1174x over previous
#include <cuda_runtime.h>
#include <cuda_bf16.h>
#include <stdint.h>

#define BATCH 4
#define CDIM  256
#define HH    120
#define WWID  120
#define SP    (HH*WWID)
#define NB    24
#define NWIN  (BATCH*NB*NB)       // 2304
#define NPOS  (BATCH*SP)          // 57600
#define QSCALE 0.17677669529663688f

#define NEGW  (-0.5f)
#define POSW  (4.0f/3.0f)
#define NORW  (-0.375f)
#define CNORW (4.0f)
#define PW    (1.8333333333333333f)   // POSW - NEGW
#define C0W   (4.375f)                // CNORW - NORW

// fp32 projections (read by attn)
__device__ float g_xk[NPOS*CDIM];
__device__ float g_xv[NPOS*CDIM];
__device__ float g_xq[NPOS*CDIM];
// bf16 split inputs for MMA
__device__ __nv_bfloat16 g_xh[NPOS*CDIM];
__device__ __nv_bfloat16 g_xl[NPOS*CDIM];
__device__ __nv_bfloat16 g_yh[NPOS*CDIM];
__device__ __nv_bfloat16 g_yl[NPOS*CDIM];
__device__ __nv_bfloat16 g_wh[4*CDIM*CDIM];   // Wk,Wv,Wq,Wout
__device__ __nv_bfloat16 g_wl[4*CDIM*CDIM];

__device__ __forceinline__ uint32_t sptr(const void* p) {
    return (uint32_t)__cvta_generic_to_shared(p);
}

#define LDM_X4(R, A) asm volatile( \
    "ldmatrix.sync.aligned.m8n8.x4.shared.b16 {%0,%1,%2,%3}, [%4];" \
    : "=r"((R)[0]), "=r"((R)[1]), "=r"((R)[2]), "=r"((R)[3]) : "r"(A))

#define MMA_BF16(D, A, B0, B1) asm volatile( \
    "mma.sync.aligned.m16n8k16.row.col.f32.bf16.bf16.f32 " \
    "{%0,%1,%2,%3},{%4,%5,%6,%7},{%8,%9},{%0,%1,%2,%3};" \
    : "+f"((D)[0]), "+f"((D)[1]), "+f"((D)[2]), "+f"((D)[3]) \
    : "r"((A)[0]), "r"((A)[1]), "r"((A)[2]), "r"((A)[3]), "r"(B0), "r"(B1))

#define CP_ASYNC16(dst, src) asm volatile( \
    "cp.async.cg.shared.global [%0], [%1], 16;" :: "r"(dst), "l"(src))
#define CP_COMMIT() asm volatile("cp.async.commit_group;")
#define CP_WAIT1()  asm volatile("cp.async.wait_group 1;")
#define CP_WAIT0()  asm volatile("cp.async.wait_group 0;")

// ---- packed f32x2 (Blackwell sm_100+) ----
#define FMA2(d, a, b) asm("fma.rn.f32x2 %0, %1, %2, %0;" : "+l"(d) : "l"(a), "l"(b))
#define ADD2(d, a, b) asm("add.rn.f32x2 %0, %1, %2;" : "=l"(d) : "l"(a), "l"(b))
#define PACK2(d, s)   asm("mov.b64 %0, {%1, %1};" : "=l"(d) : "r"(s))
#define UNPACK2(lo, hi, v) asm("mov.b64 {%0, %1}, %2;" : "=r"(lo), "=r"(hi) : "l"(v))

// ---------------------------------------------------------------------------
// Convert x [b][k][p] fp32 -> g_xh/g_xl [b*SP + p][k] bf16 hi/lo (transpose)
// ---------------------------------------------------------------------------
__global__ __launch_bounds__(256) void convertX_kernel(const float* __restrict__ x)
{
    __shared__ float st[64][65];
    const int p0 = blockIdx.x * 64;
    const int k0 = blockIdx.y * 64;
    const int b  = blockIdx.z;
    const int t  = threadIdx.x;

    for (int idx = t; idx < 4096; idx += 256) {
        const int k = idx >> 6, p = idx & 63;
        st[k][p] = x[((size_t)b * CDIM + k0 + k) * SP + p0 + p];
    }
    __syncthreads();
    for (int idx = t; idx < 2048; idx += 256) {
        const int p = idx >> 5, kk = idx & 31, k = kk * 2;
        const float v0 = st[k][p], v1 = st[k + 1][p];
        const __nv_bfloat16 h0 = __float2bfloat16(v0);
        const __nv_bfloat16 h1 = __float2bfloat16(v1);
        const __nv_bfloat16 l0 = __float2bfloat16(v0 - __bfloat162float(h0));
        const __nv_bfloat16 l1 = __float2bfloat16(v1 - __bfloat162float(h1));
        const size_t o = ((size_t)b * SP + p0 + p) * CDIM + k0 + k;
        *(__nv_bfloat162*)&g_xh[o] = __halves2bfloat162(h0, h1);
        *(__nv_bfloat162*)&g_xl[o] = __halves2bfloat162(l0, l1);
    }
}

__global__ __launch_bounds__(256) void convertW_kernel(
    const float* __restrict__ Wk, const float* __restrict__ Wv,
    const float* __restrict__ Wq, const float* __restrict__ Wout)
{
    const int i = blockIdx.x * 256 + threadIdx.x;   // 0..65535
    const float* srcs[4] = {Wk, Wv, Wq, Wout};
#pragma unroll
    for (int m = 0; m < 4; m++) {
        const float v = srcs[m][i];
        const __nv_bfloat16 h = __float2bfloat16(v);
        g_wh[m * 65536 + i] = h;
        g_wl[m * 65536 + i] = __float2bfloat16(v - __bfloat162float(h));
    }
}

// ---------------------------------------------------------------------------
// proj3 via mma.sync, cp.async double-buffered.  KC=32, 8 chunks.
// ---------------------------------------------------------------------------
#define PJ_STAGE 51200
#define PJ_SMEM  (2*PJ_STAGE)      // 102400

__device__ __forceinline__ void pj_load_chunk(char* base, int t, int row0, int c0,
                                              int chunk)
{
    const int kc = chunk * 32;
    for (int i = t; i < 1024; i += 256) {
        const int half = i >> 9, r = (i >> 2) & 127, seg = i & 3;
        const __nv_bfloat16* src = (half ? g_xl : g_xh)
            + (size_t)(row0 + r) * CDIM + kc + seg * 8;
        CP_ASYNC16(sptr(base + half * 10240 + r * 80 + seg * 16), src);
    }
    for (int i = t; i < 1536; i += 256) {
        const int half = (i >= 768), rem = i - half * 768;
        const int pr = rem >> 8, rr = (rem >> 2) & 63, seg = rem & 3;
        const __nv_bfloat16* src = (half ? g_wl : g_wh)
            + (size_t)pr * 65536 + (size_t)(c0 + rr) * CDIM + kc + seg * 8;
        CP_ASYNC16(sptr(base + 20480 + half * 15360 + pr * 5120 + rr * 80 + seg * 16),
                   src);
    }
}

__global__ __launch_bounds__(256, 2) void proj_mma_kernel()
{
    extern __shared__ char smem[];
    const int t = threadIdx.x;
    const int warp = t >> 5, lane = t & 31;
    const int wm = warp >> 1, wn = warp & 1;
    const int row0 = blockIdx.x * 128;
    const int c0   = blockIdx.y * 64;

    float acc[3][2][4][4];
#pragma unroll
    for (int a = 0; a < 3; a++)
#pragma unroll
        for (int b = 0; b < 2; b++)
#pragma unroll
            for (int c = 0; c < 4; c++)
#pragma unroll
                for (int d = 0; d < 4; d++) acc[a][b][c][d] = 0.f;

    pj_load_chunk(smem, t, row0, c0, 0);
    CP_COMMIT();

    for (int ch = 0; ch < 8; ch++) {
        if (ch < 7) {
            pj_load_chunk(smem + ((ch + 1) & 1) * PJ_STAGE, t, row0, c0, ch + 1);
            CP_COMMIT();
            CP_WAIT1();
        } else {
            CP_WAIT0();
        }
        __syncthreads();
        char* base = smem + (ch & 1) * PJ_STAGE;

#pragma unroll
        for (int ks = 0; ks < 2; ks++) {
            uint32_t Ah[2][4], Al[2][4];
            const int colb = ks * 32 + ((lane >> 4) << 4);
#pragma unroll
            for (int mt = 0; mt < 2; mt++) {
                const int r = wm * 32 + mt * 16 + (lane & 15);
                LDM_X4(Ah[mt], sptr(base + r * 80 + colb));
                LDM_X4(Al[mt], sptr(base + 10240 + r * 80 + colb));
            }
#pragma unroll
            for (int pr = 0; pr < 3; pr++) {
#pragma unroll
                for (int pair = 0; pair < 2; pair++) {
                    const int nr = wn * 32 + pair * 16 + (lane & 15);
                    uint32_t bh[4], bl[4];
                    LDM_X4(bh, sptr(base + 20480 + pr * 5120 + nr * 80 + colb));
                    LDM_X4(bl, sptr(base + 35840 + pr * 5120 + nr * 80 + colb));
#pragma unroll
                    for (int mt = 0; mt < 2; mt++) {
#pragma unroll
                        for (int sub = 0; sub < 2; sub++) {
                            const int nt = pair * 2 + sub;
                            MMA_BF16(acc[pr][mt][nt], Ah[mt], bh[sub], bh[sub + 2]);
                            MMA_BF16(acc[pr][mt][nt], Ah[mt], bl[sub], bl[sub + 2]);
                            MMA_BF16(acc[pr][mt][nt], Al[mt], bh[sub], bh[sub + 2]);
                        }
                    }
                }
            }
        }
        __syncthreads();
    }

    const int rbase = row0 + wm * 32 + (lane >> 2);
    const int cbase = c0 + wn * 32 + (lane & 3) * 2;
    float* dsts[3] = {g_xk, g_xv, g_xq};
#pragma unroll
    for (int pr = 0; pr < 3; pr++) {
        const float s = (pr == 2) ? QSCALE : 1.f;
#pragma unroll
        for (int mt = 0; mt < 2; mt++) {
#pragma unroll
            for (int nt = 0; nt < 4; nt++) {
                const int r = rbase + mt * 16;
                const int c = cbase + nt * 8;
                float* d = dsts[pr];
                *(float2*)&d[(size_t)r * CDIM + c] =
                    make_float2(acc[pr][mt][nt][0] * s, acc[pr][mt][nt][1] * s);
                *(float2*)&d[(size_t)(r + 8) * CDIM + c] =
                    make_float2(acc[pr][mt][nt][2] * s, acc[pr][mt][nt][3] * s);
            }
        }
    }
}

// ---------------------------------------------------------------------------
// attn: CTA = (window, head-half). 128 threads = 4 warps = 4 heads,
// lane = q (lanes 25-31 idle in compute).  All inner-loop LDS are warp-wide
// broadcasts (single address per warp) -> 1 wavefront each.
// ---------------------------------------------------------------------------
#define ATTN_SMEM_BYTES (2 * 4 * 49 * 36 * 4)
__global__ __launch_bounds__(128) void attn_kernel()
{
    extern __shared__ float sm_att[];
    float* sK = sm_att;
    float* sV = sm_att + 4 * 49 * 36;

    const int blk  = blockIdx.x;
    const int half = blockIdx.y;
    const int b    = blk / (NB * NB);
    const int wrem = blk % (NB * NB);
    const int wy = wrem / NB, wx = wrem % NB;
    const int t = threadIdx.x;
    const int c0 = half * 128;

    const int ky0 = wy * 5 - 1, kx0 = wx * 5 - 1;
    for (int idx = t; idx < 49 * 32; idx += 128) {
        const int r  = idx >> 5;
        const int c4 = idx & 31;
        const int y  = ky0 + r / 7;
        const int xx = kx0 + r % 7;
        float4 vk = make_float4(0.f, 0.f, 0.f, 0.f);
        float4 vv = make_float4(0.f, 0.f, 0.f, 0.f);
        if (y >= 0 && y < HH && xx >= 0 && xx < WWID) {
            const size_t g = ((size_t)b * SP + y * WWID + xx) * CDIM + c0 + c4 * 4;
            vk = *(const float4*)&g_xk[g];
            vv = *(const float4*)&g_xv[g];
        }
        const int f = c4 * 4, hl = f >> 5, cc = f & 31;
        *(float4*)&sK[(hl * 49 + r) * 36 + cc] = vk;
        *(float4*)&sV[(hl * 49 + r) * 36 + cc] = vv;
    }
    __syncthreads();

    const int lane = t & 31;
    const int hl   = t >> 5;          // warp = head within this half
    if (lane < 25) {
        const int q = lane;
        const int qy = q / 5, qx = q % 5;
        const size_t qpos = ((size_t)b * SP + (wy * 5 + qy) * WWID + wx * 5 + qx) * CDIM
                            + (half * 4 + hl) * 32;

        // Q as 16 packed f32x2
        unsigned long long qp[16];
#pragma unroll
        for (int j = 0; j < 8; j++) {
            const ulonglong2 v = *(const ulonglong2*)&g_xq[qpos + j * 4];
            qp[2*j] = v.x; qp[2*j+1] = v.y;
        }

        // S[p] = Q . K_p  (packed; K loads are warp-wide broadcasts)
        float S[49];
#pragma unroll
        for (int p = 0; p < 49; p++) {
            const float* kr = &sK[(hl * 49 + p) * 36];
            unsigned long long a0 = 0ull, a1 = 0ull;
#pragma unroll
            for (int j = 0; j < 8; j++) {
                const ulonglong2 kv = *(const ulonglong2*)&kr[j * 4];
                FMA2(a0, qp[2*j],   kv.x);
                FMA2(a1, qp[2*j+1], kv.y);
            }
            unsigned long long asum; ADD2(asum, a0, a1);
            uint32_t lo, hi; UNPACK2(lo, hi, asum);
            S[p] = __uint_as_float(lo) + __uint_as_float(hi);
        }

        float mpos = S[0], mneg = S[0];
#pragma unroll
        for (int p = 1; p < 49; p++) { mpos = fmaxf(mpos, S[p]); mneg = fminf(mneg, S[p]); }
        const float m = 4.0f * mpos - 3.0f * mneg;

        // streaming 3-row Ar window + fused AV (packed o accumulators)
        unsigned long long o2[16];
#pragma unroll
        for (int j = 0; j < 16; j++) o2[j] = 0ull;
        float A0[7], A1[7], A2[7];
#pragma unroll
        for (int j = 0; j < 7; j++) { A0[j] = 0.f; A1[j] = 0.f; A2[j] = 0.f; }

        float ssum = 0.f;
#pragma unroll
        for (int ky = 0; ky < 5; ky++) {
#pragma unroll
            for (int kx = 0; kx < 5; kx++) {
                const float c  = S[(ky+1)*7 + kx+1];
                const float u  = S[(ky  )*7 + kx+1];
                const float d  = S[(ky+2)*7 + kx+1];
                const float l  = S[(ky+1)*7 + kx  ];
                const float r  = S[(ky+1)*7 + kx+2];
                const float tl = S[(ky  )*7 + kx  ];
                const float tr = S[(ky  )*7 + kx+2];
                const float bl = S[(ky+2)*7 + kx  ];
                const float br = S[(ky+2)*7 + kx+2];
                const float s_ud = u + d, s_lr = l + r;
                const float dg = tl + br, ad = tr + bl;
                const float sum9 = ((s_ud + s_lr) + (dg + ad)) + c;
                const float base = fmaf(NEGW, sum9, -m);
                const float e0 = __expf(fmaf(NORW, sum9, fmaf(C0W, c, -m)));
                const float e1 = __expf(fmaf(PW, s_ud + c, base));
                const float e2 = __expf(fmaf(PW, s_lr + c, base));
                const float e3 = __expf(fmaf(PW, dg + c, base));
                const float e4 = __expf(fmaf(PW, ad + c, base));
                const float e5 = __expf(fmaf(PW, (u + l) + c, base));
                const float e6 = __expf(fmaf(PW, (u + r) + c, base));
                const float e7 = __expf(fmaf(PW, (l + d) + c, base));
                const float e8 = __expf(fmaf(PW, (r + d) + c, base));
                const float E = ((e1 + e2) + (e3 + e4)) + ((e5 + e6) + (e7 + e8));
                ssum += E + e0;
                const float basea = fmaf(NEGW, E, NORW * e0);
                A0[kx  ] += fmaf(PW, e3, basea);
                A0[kx+1] += fmaf(PW, (e1 + e5) + e6, basea);
                A0[kx+2] += fmaf(PW, e4, basea);
                A1[kx  ] += fmaf(PW, (e2 + e5) + e7, basea);
                A1[kx+1] += fmaf(PW, E, fmaf(C0W, e0, basea));
                A1[kx+2] += fmaf(PW, (e2 + e6) + e8, basea);
                A2[kx  ] += fmaf(PW, e4, basea);
                A2[kx+1] += fmaf(PW, (e1 + e7) + e8, basea);
                A2[kx+2] += fmaf(PW, e3, basea);
            }
            // row ky is final: fused AV (V loads broadcast warp-wide)
#pragma unroll
            for (int px = 0; px < 7; px++) {
                unsigned long long aa; PACK2(aa, __float_as_uint(A0[px]));
                const float* vr = &sV[(hl * 49 + ky * 7 + px) * 36];
#pragma unroll
                for (int j = 0; j < 8; j++) {
                    const ulonglong2 vv = *(const ulonglong2*)&vr[j * 4];
                    FMA2(o2[2*j],   aa, vv.x);
                    FMA2(o2[2*j+1], aa, vv.y);
                }
            }
            // rotate window
#pragma unroll
            for (int j = 0; j < 7; j++) { A0[j] = A1[j]; A1[j] = A2[j]; A2[j] = 0.f; }
        }
        // rows 5 (A0) and 6 (A1)
#pragma unroll
        for (int rr = 0; rr < 2; rr++) {
#pragma unroll
            for (int px = 0; px < 7; px++) {
                const float a = rr ? A1[px] : A0[px];
                unsigned long long aa; PACK2(aa, __float_as_uint(a));
                const float* vr = &sV[(hl * 49 + (5 + rr) * 7 + px) * 36];
#pragma unroll
                for (int j = 0; j < 8; j++) {
                    const ulonglong2 vv = *(const ulonglong2*)&vr[j * 4];
                    FMA2(o2[2*j],   aa, vv.x);
                    FMA2(o2[2*j+1], aa, vv.y);
                }
            }
        }

        const float inv = 1.0f / ssum;
        uint32_t hw[16], lw[16];
#pragma unroll
        for (int j = 0; j < 16; j++) {
            uint32_t lo, hi; UNPACK2(lo, hi, o2[j]);
            const float v0 = __uint_as_float(lo) * inv;
            const float v1 = __uint_as_float(hi) * inv;
            const __nv_bfloat16 h0 = __float2bfloat16(v0);
            const __nv_bfloat16 h1 = __float2bfloat16(v1);
            const __nv_bfloat16 l0 = __float2bfloat16(v0 - __bfloat162float(h0));
            const __nv_bfloat16 l1 = __float2bfloat16(v1 - __bfloat162float(h1));
            __nv_bfloat162 hp = __halves2bfloat162(h0, h1);
            __nv_bfloat162 lp = __halves2bfloat162(l0, l1);
            hw[j] = *(uint32_t*)&hp;
            lw[j] = *(uint32_t*)&lp;
        }
#pragma unroll
        for (int j = 0; j < 4; j++) {
            *(uint4*)&g_yh[qpos + j * 8] = make_uint4(hw[4*j], hw[4*j+1], hw[4*j+2], hw[4*j+3]);
            *(uint4*)&g_yl[qpos + j * 8] = make_uint4(lw[4*j], lw[4*j+1], lw[4*j+2], lw[4*j+3]);
        }
    }
}

// ---------------------------------------------------------------------------
// outproj via mma.sync, cp.async double-buffered.  KC=32, 8 chunks.
// ---------------------------------------------------------------------------
#define OP_STAGE 30720
#define OP_BIAS  (2*OP_STAGE)              // 61440, 256B bias
#define OP_SMEM  (2*OP_STAGE + 256)

__device__ __forceinline__ void op_load_chunk(char* base, int t, int row0, int c0,
                                              int chunk)
{
    const int kc = chunk * 32;
    for (int i = t; i < 1024; i += 256) {
        const int half = i >> 9, r = (i >> 2) & 127, seg = i & 3;
        const __nv_bfloat16* src = (half ? g_yl : g_yh)
            + (size_t)(row0 + r) * CDIM + kc + seg * 8;
        CP_ASYNC16(sptr(base + half * 10240 + r * 80 + seg * 16), src);
    }
    for (int i = t; i < 512; i += 256) {
        const int half = i >> 8, rr = (i >> 2) & 63, seg = i & 3;
        const __nv_bfloat16* src = (half ? g_wl : g_wh)
            + (size_t)3 * 65536 + (size_t)(c0 + rr) * CDIM + kc + seg * 8;
        CP_ASYNC16(sptr(base + 20480 + half * 5120 + rr * 80 + seg * 16), src);
    }
}

__global__ __launch_bounds__(256, 2) void outproj_mma_kernel(
    const float* __restrict__ bout, float* __restrict__ out)
{
    extern __shared__ char smem[];
    float* sT = (float*)smem;
    float* sBias = (float*)(smem + OP_BIAS);
    const int t = threadIdx.x;
    const int warp = t >> 5, lane = t & 31;
    const int wm = warp >> 1, wn = warp & 1;
    const int row0 = blockIdx.x * 128;
    const int c0   = blockIdx.y * 64;

    if (t < 64) sBias[t] = bout[c0 + t];

    float acc[2][4][4];
#pragma unroll
    for (int b = 0; b < 2; b++)
#pragma unroll
        for (int c = 0; c < 4; c++)
#pragma unroll
            for (int d = 0; d < 4; d++) acc[b][c][d] = 0.f;

    op_load_chunk(smem, t, row0, c0, 0);
    CP_COMMIT();

    for (int ch = 0; ch < 8; ch++) {
        if (ch < 7) {
            op_load_chunk(smem + ((ch + 1) & 1) * OP_STAGE, t, row0, c0, ch + 1);
            CP_COMMIT();
            CP_WAIT1();
        } else {
            CP_WAIT0();
        }
        __syncthreads();
        char* base = smem + (ch & 1) * OP_STAGE;

#pragma unroll
        for (int ks = 0; ks < 2; ks++) {
            uint32_t Ah[2][4], Al[2][4];
            const int colb = ks * 32 + ((lane >> 4) << 4);
#pragma unroll
            for (int mt = 0; mt < 2; mt++) {
                const int r = wm * 32 + mt * 16 + (lane & 15);
                LDM_X4(Ah[mt], sptr(base + r * 80 + colb));
                LDM_X4(Al[mt], sptr(base + 10240 + r * 80 + colb));
            }
#pragma unroll
            for (int pair = 0; pair < 2; pair++) {
                const int nr = wn * 32 + pair * 16 + (lane & 15);
                uint32_t bh[4], bl[4];
                LDM_X4(bh, sptr(base + 20480 + nr * 80 + colb));
                LDM_X4(bl, sptr(base + 25600 + nr * 80 + colb));
#pragma unroll
                for (int mt = 0; mt < 2; mt++) {
#pragma unroll
                    for (int sub = 0; sub < 2; sub++) {
                        const int nt = pair * 2 + sub;
                        MMA_BF16(acc[mt][nt], Ah[mt], bh[sub], bh[sub + 2]);
                        MMA_BF16(acc[mt][nt], Ah[mt], bl[sub], bl[sub + 2]);
                        MMA_BF16(acc[mt][nt], Al[mt], bh[sub], bh[sub + 2]);
                    }
                }
            }
        }
        __syncthreads();
    }

    const int rl = wm * 32 + (lane >> 2);
    const int cl = wn * 32 + (lane & 3) * 2;
#pragma unroll
    for (int mt = 0; mt < 2; mt++) {
#pragma unroll
        for (int nt = 0; nt < 4; nt++) {
            const int r = rl + mt * 16;
            const int c = cl + nt * 8;
            sT[(c    ) * 132 + r    ] = acc[mt][nt][0];
            sT[(c + 1) * 132 + r    ] = acc[mt][nt][1];
            sT[(c    ) * 132 + r + 8] = acc[mt][nt][2];
            sT[(c + 1) * 132 + r + 8] = acc[mt][nt][3];
        }
    }
    __syncthreads();

    for (int i = t; i < 8192; i += 256) {
        const int c = i >> 7, r = i & 127;
        const int pf = row0 + r;
        const int b  = pf / SP;
        const int p  = pf - b * SP;
        out[((size_t)b * CDIM + c0 + c) * SP + p] = sT[c * 132 + r] + sBias[c];
    }
}

// ---------------------------------------------------------------------------
extern "C" void kernel_launch(void* const* d_in, const int* in_sizes, int n_in,
                              void* d_out, int out_size)
{
    const float* x    = (const float*)d_in[0];
    const float* Wk   = (const float*)d_in[2];
    const float* Wv   = (const float*)d_in[3];
    const float* Wq   = (const float*)d_in[4];
    const float* Wout = (const float*)d_in[5];
    const float* bout = (const float*)d_in[6];
    float* out = (float*)d_out;

    cudaFuncSetAttribute(proj_mma_kernel, cudaFuncAttributeMaxDynamicSharedMemorySize,
                         PJ_SMEM);
    cudaFuncSetAttribute(attn_kernel, cudaFuncAttributeMaxDynamicSharedMemorySize,
                         ATTN_SMEM_BYTES);
    cudaFuncSetAttribute(outproj_mma_kernel, cudaFuncAttributeMaxDynamicSharedMemorySize,
                         OP_SMEM);

    convertX_kernel<<<dim3(SP / 64, CDIM / 64, BATCH), 256>>>(x);
    convertW_kernel<<<256, 256>>>(Wk, Wv, Wq, Wout);
    proj_mma_kernel<<<dim3(NPOS / 128, CDIM / 64), 256, PJ_SMEM>>>();
    attn_kernel<<<dim3(NWIN, 2), 128, ATTN_SMEM_BYTES>>>();
    outproj_mma_kernel<<<dim3(NPOS / 128, CDIM / 64), 256, OP_SMEM>>>(bout, out);
}

// round 10
// speedup vs baseline: 2.1705x; 1.0189x over previous
#include <cuda_runtime.h>
#include <cuda_bf16.h>
#include <stdint.h>

#define BATCH 4
#define CDIM  256
#define HH    120
#define WWID  120
#define SP    (HH*WWID)
#define NB    24
#define NWIN  (BATCH*NB*NB)       // 2304
#define NPOS  (BATCH*SP)          // 57600
#define QSCALE 0.17677669529663688f

#define NEGW  (-0.5f)
#define POSW  (4.0f/3.0f)
#define NORW  (-0.375f)
#define CNORW (4.0f)
#define PW    (1.8333333333333333f)   // POSW - NEGW
#define C0W   (4.375f)                // CNORW - NORW

// fp32 projections (read by attn)
__device__ float g_xk[NPOS*CDIM];
__device__ float g_xv[NPOS*CDIM];
__device__ float g_xq[NPOS*CDIM];
// bf16 split inputs for MMA
__device__ __nv_bfloat16 g_xh[NPOS*CDIM];
__device__ __nv_bfloat16 g_xl[NPOS*CDIM];
__device__ __nv_bfloat16 g_yh[NPOS*CDIM];
__device__ __nv_bfloat16 g_yl[NPOS*CDIM];
__device__ __nv_bfloat16 g_wh[4*CDIM*CDIM];   // Wk,Wv,Wq,Wout
__device__ __nv_bfloat16 g_wl[4*CDIM*CDIM];

__device__ __forceinline__ uint32_t sptr(const void* p) {
    return (uint32_t)__cvta_generic_to_shared(p);
}

#define LDM_X4(R, A) asm volatile( \
    "ldmatrix.sync.aligned.m8n8.x4.shared.b16 {%0,%1,%2,%3}, [%4];" \
    : "=r"((R)[0]), "=r"((R)[1]), "=r"((R)[2]), "=r"((R)[3]) : "r"(A))

#define MMA_BF16(D, A, B0, B1) asm volatile( \
    "mma.sync.aligned.m16n8k16.row.col.f32.bf16.bf16.f32 " \
    "{%0,%1,%2,%3},{%4,%5,%6,%7},{%8,%9},{%0,%1,%2,%3};" \
    : "+f"((D)[0]), "+f"((D)[1]), "+f"((D)[2]), "+f"((D)[3]) \
    : "r"((A)[0]), "r"((A)[1]), "r"((A)[2]), "r"((A)[3]), "r"(B0), "r"(B1))

#define CP_ASYNC16(dst, src) asm volatile( \
    "cp.async.cg.shared.global [%0], [%1], 16;" :: "r"(dst), "l"(src))
#define CP_COMMIT() asm volatile("cp.async.commit_group;")
#define CP_WAIT1()  asm volatile("cp.async.wait_group 1;")
#define CP_WAIT0()  asm volatile("cp.async.wait_group 0;")

// ---- packed f32x2 (Blackwell sm_100+) ----
#define FMA2(d, a, b) asm("fma.rn.f32x2 %0, %1, %2, %0;" : "+l"(d) : "l"(a), "l"(b))
#define ADD2(d, a, b) asm("add.rn.f32x2 %0, %1, %2;" : "=l"(d) : "l"(a), "l"(b))
#define PACK2(d, s)   asm("mov.b64 %0, {%1, %1};" : "=l"(d) : "r"(s))
#define UNPACK2(lo, hi, v) asm("mov.b64 {%0, %1}, %2;" : "=r"(lo), "=r"(hi) : "l"(v))

// ---------------------------------------------------------------------------
// Convert x [b][k][p] fp32 -> g_xh/g_xl [b*SP + p][k] bf16 hi/lo (transpose)
// ---------------------------------------------------------------------------
__global__ __launch_bounds__(256) void convertX_kernel(const float* __restrict__ x)
{
    __shared__ float st[64][65];
    const int p0 = blockIdx.x * 64;
    const int k0 = blockIdx.y * 64;
    const int b  = blockIdx.z;
    const int t  = threadIdx.x;

    for (int idx = t; idx < 4096; idx += 256) {
        const int k = idx >> 6, p = idx & 63;
        st[k][p] = x[((size_t)b * CDIM + k0 + k) * SP + p0 + p];
    }
    __syncthreads();
    for (int idx = t; idx < 2048; idx += 256) {
        const int p = idx >> 5, kk = idx & 31, k = kk * 2;
        const float v0 = st[k][p], v1 = st[k + 1][p];
        const __nv_bfloat16 h0 = __float2bfloat16(v0);
        const __nv_bfloat16 h1 = __float2bfloat16(v1);
        const __nv_bfloat16 l0 = __float2bfloat16(v0 - __bfloat162float(h0));
        const __nv_bfloat16 l1 = __float2bfloat16(v1 - __bfloat162float(h1));
        const size_t o = ((size_t)b * SP + p0 + p) * CDIM + k0 + k;
        *(__nv_bfloat162*)&g_xh[o] = __halves2bfloat162(h0, h1);
        *(__nv_bfloat162*)&g_xl[o] = __halves2bfloat162(l0, l1);
    }
}

__global__ __launch_bounds__(256) void convertW_kernel(
    const float* __restrict__ Wk, const float* __restrict__ Wv,
    const float* __restrict__ Wq, const float* __restrict__ Wout)
{
    const int i = blockIdx.x * 256 + threadIdx.x;   // 0..65535
    const float* srcs[4] = {Wk, Wv, Wq, Wout};
#pragma unroll
    for (int m = 0; m < 4; m++) {
        const float v = srcs[m][i];
        const __nv_bfloat16 h = __float2bfloat16(v);
        g_wh[m * 65536 + i] = h;
        g_wl[m * 65536 + i] = __float2bfloat16(v - __bfloat162float(h));
    }
}

// ---------------------------------------------------------------------------
// proj3 via mma.sync, cp.async double-buffered.  KC=32, 8 chunks.
// ---------------------------------------------------------------------------
#define PJ_STAGE 51200
#define PJ_SMEM  (2*PJ_STAGE)      // 102400

__device__ __forceinline__ void pj_load_chunk(char* base, int t, int row0, int c0,
                                              int chunk)
{
    const int kc = chunk * 32;
    for (int i = t; i < 1024; i += 256) {
        const int half = i >> 9, r = (i >> 2) & 127, seg = i & 3;
        const __nv_bfloat16* src = (half ? g_xl : g_xh)
            + (size_t)(row0 + r) * CDIM + kc + seg * 8;
        CP_ASYNC16(sptr(base + half * 10240 + r * 80 + seg * 16), src);
    }
    for (int i = t; i < 1536; i += 256) {
        const int half = (i >= 768), rem = i - half * 768;
        const int pr = rem >> 8, rr = (rem >> 2) & 63, seg = rem & 3;
        const __nv_bfloat16* src = (half ? g_wl : g_wh)
            + (size_t)pr * 65536 + (size_t)(c0 + rr) * CDIM + kc + seg * 8;
        CP_ASYNC16(sptr(base + 20480 + half * 15360 + pr * 5120 + rr * 80 + seg * 16),
                   src);
    }
}

__global__ __launch_bounds__(256, 2) void proj_mma_kernel()
{
    extern __shared__ char smem[];
    const int t = threadIdx.x;
    const int warp = t >> 5, lane = t & 31;
    const int wm = warp >> 1, wn = warp & 1;
    const int row0 = blockIdx.x * 128;
    const int c0   = blockIdx.y * 64;

    float acc[3][2][4][4];
#pragma unroll
    for (int a = 0; a < 3; a++)
#pragma unroll
        for (int b = 0; b < 2; b++)
#pragma unroll
            for (int c = 0; c < 4; c++)
#pragma unroll
                for (int d = 0; d < 4; d++) acc[a][b][c][d] = 0.f;

    pj_load_chunk(smem, t, row0, c0, 0);
    CP_COMMIT();

    for (int ch = 0; ch < 8; ch++) {
        if (ch < 7) {
            pj_load_chunk(smem + ((ch + 1) & 1) * PJ_STAGE, t, row0, c0, ch + 1);
            CP_COMMIT();
            CP_WAIT1();
        } else {
            CP_WAIT0();
        }
        __syncthreads();
        char* base = smem + (ch & 1) * PJ_STAGE;

#pragma unroll
        for (int ks = 0; ks < 2; ks++) {
            uint32_t Ah[2][4], Al[2][4];
            const int colb = ks * 32 + ((lane >> 4) << 4);
#pragma unroll
            for (int mt = 0; mt < 2; mt++) {
                const int r = wm * 32 + mt * 16 + (lane & 15);
                LDM_X4(Ah[mt], sptr(base + r * 80 + colb));
                LDM_X4(Al[mt], sptr(base + 10240 + r * 80 + colb));
            }
#pragma unroll
            for (int pr = 0; pr < 3; pr++) {
#pragma unroll
                for (int pair = 0; pair < 2; pair++) {
                    const int nr = wn * 32 + pair * 16 + (lane & 15);
                    uint32_t bh[4], bl[4];
                    LDM_X4(bh, sptr(base + 20480 + pr * 5120 + nr * 80 + colb));
                    LDM_X4(bl, sptr(base + 35840 + pr * 5120 + nr * 80 + colb));
#pragma unroll
                    for (int mt = 0; mt < 2; mt++) {
#pragma unroll
                        for (int sub = 0; sub < 2; sub++) {
                            const int nt = pair * 2 + sub;
                            MMA_BF16(acc[pr][mt][nt], Ah[mt], bh[sub], bh[sub + 2]);
                            MMA_BF16(acc[pr][mt][nt], Ah[mt], bl[sub], bl[sub + 2]);
                            MMA_BF16(acc[pr][mt][nt], Al[mt], bh[sub], bh[sub + 2]);
                        }
                    }
                }
            }
        }
        __syncthreads();
    }

    const int rbase = row0 + wm * 32 + (lane >> 2);
    const int cbase = c0 + wn * 32 + (lane & 3) * 2;
    float* dsts[3] = {g_xk, g_xv, g_xq};
#pragma unroll
    for (int pr = 0; pr < 3; pr++) {
        const float s = (pr == 2) ? QSCALE : 1.f;
#pragma unroll
        for (int mt = 0; mt < 2; mt++) {
#pragma unroll
            for (int nt = 0; nt < 4; nt++) {
                const int r = rbase + mt * 16;
                const int c = cbase + nt * 8;
                float* d = dsts[pr];
                *(float2*)&d[(size_t)r * CDIM + c] =
                    make_float2(acc[pr][mt][nt][0] * s, acc[pr][mt][nt][1] * s);
                *(float2*)&d[(size_t)(r + 8) * CDIM + c] =
                    make_float2(acc[pr][mt][nt][2] * s, acc[pr][mt][nt][3] * s);
            }
        }
    }
}

// ---------------------------------------------------------------------------
// attn: CTA = (window, head-half). 128 threads = 4 warps = 4 heads, lane = q.
// Phase 1: S row per lane (f32x2), then spilled to smem overlaying dead sK
// (lane-private, conflict-free: 49 mod 32 = 17).  Phase 2: logits read S via
// rolling 3-column window; fused AV over broadcast sV.  Regs < 128 -> 4 CTAs/SM.
// ---------------------------------------------------------------------------
#define ATTN_SMEM_BYTES (2 * 4 * 49 * 32 * 4)   // 50176
__global__ __launch_bounds__(128, 4) void attn_kernel()
{
    extern __shared__ float sm_att[];
    float* sK = sm_att;                // 6272 floats; dead after phase 1
    float* sV = sm_att + 4 * 49 * 32;

    const int blk  = blockIdx.x;
    const int half = blockIdx.y;
    const int b    = blk / (NB * NB);
    const int wrem = blk % (NB * NB);
    const int wy = wrem / NB, wx = wrem % NB;
    const int t = threadIdx.x;
    const int c0 = half * 128;

    const int ky0 = wy * 5 - 1, kx0 = wx * 5 - 1;
    for (int idx = t; idx < 49 * 32; idx += 128) {
        const int r  = idx >> 5;
        const int c4 = idx & 31;
        const int y  = ky0 + r / 7;
        const int xx = kx0 + r % 7;
        float4 vk = make_float4(0.f, 0.f, 0.f, 0.f);
        float4 vv = make_float4(0.f, 0.f, 0.f, 0.f);
        if (y >= 0 && y < HH && xx >= 0 && xx < WWID) {
            const size_t g = ((size_t)b * SP + y * WWID + xx) * CDIM + c0 + c4 * 4;
            vk = *(const float4*)&g_xk[g];
            vv = *(const float4*)&g_xv[g];
        }
        const int f = c4 * 4, hl = f >> 5, cc = f & 31;
        *(float4*)&sK[(hl * 49 + r) * 32 + cc] = vk;
        *(float4*)&sV[(hl * 49 + r) * 32 + cc] = vv;
    }
    __syncthreads();

    const int lane = t & 31;
    const int hl   = t >> 5;          // warp = head within this half
    if (lane < 25) {
        const int q = lane;
        const int qy = q / 5, qx = q % 5;
        const size_t qpos = ((size_t)b * SP + (wy * 5 + qy) * WWID + wx * 5 + qx) * CDIM
                            + (half * 4 + hl) * 32;
        float* Sr = &sm_att[t * 49];  // lane-private S row (overlays own dead K strip)

        float m;
        {
            // Q as 16 packed f32x2
            unsigned long long qp[16];
#pragma unroll
            for (int j = 0; j < 8; j++) {
                const ulonglong2 v = *(const ulonglong2*)&g_xq[qpos + j * 4];
                qp[2*j] = v.x; qp[2*j+1] = v.y;
            }

            // S[p] = Q . K_p  (K loads warp-wide broadcasts)
            float S[49];
#pragma unroll
            for (int p = 0; p < 49; p++) {
                const float* kr = &sK[(hl * 49 + p) * 32];
                unsigned long long a0 = 0ull, a1 = 0ull;
#pragma unroll
                for (int j = 0; j < 8; j++) {
                    const ulonglong2 kv = *(const ulonglong2*)&kr[j * 4];
                    FMA2(a0, qp[2*j],   kv.x);
                    FMA2(a1, qp[2*j+1], kv.y);
                }
                unsigned long long asum; ADD2(asum, a0, a1);
                uint32_t lo, hi; UNPACK2(lo, hi, asum);
                S[p] = __uint_as_float(lo) + __uint_as_float(hi);
            }
            float mpos = S[0], mneg = S[0];
#pragma unroll
            for (int p = 1; p < 49; p++) { mpos = fmaxf(mpos, S[p]); mneg = fminf(mneg, S[p]); }
            m = 4.0f * mpos - 3.0f * mneg;
            // spill S to lane-private smem (intra-warp lockstep: all computes done)
#pragma unroll
            for (int p = 0; p < 49; p++) Sr[p] = S[p];
        }

        // phase 2: streaming 3-row A window + fused AV
        unsigned long long o2[16];
#pragma unroll
        for (int j = 0; j < 16; j++) o2[j] = 0ull;
        float A0[7], A1[7], A2[7];
#pragma unroll
        for (int j = 0; j < 7; j++) { A0[j] = 0.f; A1[j] = 0.f; A2[j] = 0.f; }

        float ssum = 0.f;
#pragma unroll
        for (int ky = 0; ky < 5; ky++) {
            // rolling 3x3 column window over S rows ky..ky+2
            float a0 = Sr[ky*7],     a1 = Sr[(ky+1)*7],     a2 = Sr[(ky+2)*7];
            float b0 = Sr[ky*7 + 1], b1 = Sr[(ky+1)*7 + 1], b2 = Sr[(ky+2)*7 + 1];
#pragma unroll
            for (int kx = 0; kx < 5; kx++) {
                const float t0 = Sr[ky*7 + kx + 2];
                const float t1 = Sr[(ky+1)*7 + kx + 2];
                const float t2 = Sr[(ky+2)*7 + kx + 2];
                const float tl = a0, l = a1, bl = a2;
                const float u  = b0, c = b1, d  = b2;
                const float tr = t0, r = t1, br = t2;
                const float s_ud = u + d, s_lr = l + r;
                const float dg = tl + br, ad = tr + bl;
                const float sum9 = ((s_ud + s_lr) + (dg + ad)) + c;
                const float base = fmaf(NEGW, sum9, -m);
                const float e0 = __expf(fmaf(NORW, sum9, fmaf(C0W, c, -m)));
                const float e1 = __expf(fmaf(PW, s_ud + c, base));
                const float e2 = __expf(fmaf(PW, s_lr + c, base));
                const float e3 = __expf(fmaf(PW, dg + c, base));
                const float e4 = __expf(fmaf(PW, ad + c, base));
                const float e5 = __expf(fmaf(PW, (u + l) + c, base));
                const float e6 = __expf(fmaf(PW, (u + r) + c, base));
                const float e7 = __expf(fmaf(PW, (l + d) + c, base));
                const float e8 = __expf(fmaf(PW, (r + d) + c, base));
                const float E = ((e1 + e2) + (e3 + e4)) + ((e5 + e6) + (e7 + e8));
                ssum += E + e0;
                const float basea = fmaf(NEGW, E, NORW * e0);
                A0[kx  ] += fmaf(PW, e3, basea);
                A0[kx+1] += fmaf(PW, (e1 + e5) + e6, basea);
                A0[kx+2] += fmaf(PW, e4, basea);
                A1[kx  ] += fmaf(PW, (e2 + e5) + e7, basea);
                A1[kx+1] += fmaf(PW, E, fmaf(C0W, e0, basea));
                A1[kx+2] += fmaf(PW, (e2 + e6) + e8, basea);
                A2[kx  ] += fmaf(PW, e4, basea);
                A2[kx+1] += fmaf(PW, (e1 + e7) + e8, basea);
                A2[kx+2] += fmaf(PW, e3, basea);
                a0 = b0; a1 = b1; a2 = b2;
                b0 = t0; b1 = t1; b2 = t2;
            }
            // row ky is final: fused AV (V loads broadcast warp-wide)
#pragma unroll
            for (int px = 0; px < 7; px++) {
                unsigned long long aa; PACK2(aa, __float_as_uint(A0[px]));
                const float* vr = &sV[(hl * 49 + ky * 7 + px) * 32];
#pragma unroll
                for (int j = 0; j < 8; j++) {
                    const ulonglong2 vv = *(const ulonglong2*)&vr[j * 4];
                    FMA2(o2[2*j],   aa, vv.x);
                    FMA2(o2[2*j+1], aa, vv.y);
                }
            }
#pragma unroll
            for (int j = 0; j < 7; j++) { A0[j] = A1[j]; A1[j] = A2[j]; A2[j] = 0.f; }
        }
        // rows 5 (A0) and 6 (A1)
#pragma unroll
        for (int rr = 0; rr < 2; rr++) {
#pragma unroll
            for (int px = 0; px < 7; px++) {
                const float a = rr ? A1[px] : A0[px];
                unsigned long long aa; PACK2(aa, __float_as_uint(a));
                const float* vr = &sV[(hl * 49 + (5 + rr) * 7 + px) * 32];
#pragma unroll
                for (int j = 0; j < 8; j++) {
                    const ulonglong2 vv = *(const ulonglong2*)&vr[j * 4];
                    FMA2(o2[2*j],   aa, vv.x);
                    FMA2(o2[2*j+1], aa, vv.y);
                }
            }
        }

        const float inv = 1.0f / ssum;
        uint32_t hw[16], lw[16];
#pragma unroll
        for (int j = 0; j < 16; j++) {
            uint32_t lo, hi; UNPACK2(lo, hi, o2[j]);
            const float v0 = __uint_as_float(lo) * inv;
            const float v1 = __uint_as_float(hi) * inv;
            const __nv_bfloat16 h0 = __float2bfloat16(v0);
            const __nv_bfloat16 h1 = __float2bfloat16(v1);
            const __nv_bfloat16 l0 = __float2bfloat16(v0 - __bfloat162float(h0));
            const __nv_bfloat16 l1 = __float2bfloat16(v1 - __bfloat162float(h1));
            __nv_bfloat162 hp = __halves2bfloat162(h0, h1);
            __nv_bfloat162 lp = __halves2bfloat162(l0, l1);
            hw[j] = *(uint32_t*)&hp;
            lw[j] = *(uint32_t*)&lp;
        }
#pragma unroll
        for (int j = 0; j < 4; j++) {
            *(uint4*)&g_yh[qpos + j * 8] = make_uint4(hw[4*j], hw[4*j+1], hw[4*j+2], hw[4*j+3]);
            *(uint4*)&g_yl[qpos + j * 8] = make_uint4(lw[4*j], lw[4*j+1], lw[4*j+2], lw[4*j+3]);
        }
    }
}

// ---------------------------------------------------------------------------
// outproj via mma.sync, cp.async double-buffered.  KC=32, 8 chunks.
// ---------------------------------------------------------------------------
#define OP_STAGE 30720
#define OP_BIAS  (2*OP_STAGE)              // 61440, 256B bias
#define OP_SMEM  (2*OP_STAGE + 256)

__device__ __forceinline__ void op_load_chunk(char* base, int t, int row0, int c0,
                                              int chunk)
{
    const int kc = chunk * 32;
    for (int i = t; i < 1024; i += 256) {
        const int half = i >> 9, r = (i >> 2) & 127, seg = i & 3;
        const __nv_bfloat16* src = (half ? g_yl : g_yh)
            + (size_t)(row0 + r) * CDIM + kc + seg * 8;
        CP_ASYNC16(sptr(base + half * 10240 + r * 80 + seg * 16), src);
    }
    for (int i = t; i < 512; i += 256) {
        const int half = i >> 8, rr = (i >> 2) & 63, seg = i & 3;
        const __nv_bfloat16* src = (half ? g_wl : g_wh)
            + (size_t)3 * 65536 + (size_t)(c0 + rr) * CDIM + kc + seg * 8;
        CP_ASYNC16(sptr(base + 20480 + half * 5120 + rr * 80 + seg * 16), src);
    }
}

__global__ __launch_bounds__(256, 2) void outproj_mma_kernel(
    const float* __restrict__ bout, float* __restrict__ out)
{
    extern __shared__ char smem[];
    float* sT = (float*)smem;
    float* sBias = (float*)(smem + OP_BIAS);
    const int t = threadIdx.x;
    const int warp = t >> 5, lane = t & 31;
    const int wm = warp >> 1, wn = warp & 1;
    const int row0 = blockIdx.x * 128;
    const int c0   = blockIdx.y * 64;

    if (t < 64) sBias[t] = bout[c0 + t];

    float acc[2][4][4];
#pragma unroll
    for (int b = 0; b < 2; b++)
#pragma unroll
        for (int c = 0; c < 4; c++)
#pragma unroll
            for (int d = 0; d < 4; d++) acc[b][c][d] = 0.f;

    op_load_chunk(smem, t, row0, c0, 0);
    CP_COMMIT();

    for (int ch = 0; ch < 8; ch++) {
        if (ch < 7) {
            op_load_chunk(smem + ((ch + 1) & 1) * OP_STAGE, t, row0, c0, ch + 1);
            CP_COMMIT();
            CP_WAIT1();
        } else {
            CP_WAIT0();
        }
        __syncthreads();
        char* base = smem + (ch & 1) * OP_STAGE;

#pragma unroll
        for (int ks = 0; ks < 2; ks++) {
            uint32_t Ah[2][4], Al[2][4];
            const int colb = ks * 32 + ((lane >> 4) << 4);
#pragma unroll
            for (int mt = 0; mt < 2; mt++) {
                const int r = wm * 32 + mt * 16 + (lane & 15);
                LDM_X4(Ah[mt], sptr(base + r * 80 + colb));
                LDM_X4(Al[mt], sptr(base + 10240 + r * 80 + colb));
            }
#pragma unroll
            for (int pair = 0; pair < 2; pair++) {
                const int nr = wn * 32 + pair * 16 + (lane & 15);
                uint32_t bh[4], bl[4];
                LDM_X4(bh, sptr(base + 20480 + nr * 80 + colb));
                LDM_X4(bl, sptr(base + 25600 + nr * 80 + colb));
#pragma unroll
                for (int mt = 0; mt < 2; mt++) {
#pragma unroll
                    for (int sub = 0; sub < 2; sub++) {
                        const int nt = pair * 2 + sub;
                        MMA_BF16(acc[mt][nt], Ah[mt], bh[sub], bh[sub + 2]);
                        MMA_BF16(acc[mt][nt], Ah[mt], bl[sub], bl[sub + 2]);
                        MMA_BF16(acc[mt][nt], Al[mt], bh[sub], bh[sub + 2]);
                    }
                }
            }
        }
        __syncthreads();
    }

    const int rl = wm * 32 + (lane >> 2);
    const int cl = wn * 32 + (lane & 3) * 2;
#pragma unroll
    for (int mt = 0; mt < 2; mt++) {
#pragma unroll
        for (int nt = 0; nt < 4; nt++) {
            const int r = rl + mt * 16;
            const int c = cl + nt * 8;
            sT[(c    ) * 132 + r    ] = acc[mt][nt][0];
            sT[(c + 1) * 132 + r    ] = acc[mt][nt][1];
            sT[(c    ) * 132 + r + 8] = acc[mt][nt][2];
            sT[(c + 1) * 132 + r + 8] = acc[mt][nt][3];
        }
    }
    __syncthreads();

    for (int i = t; i < 8192; i += 256) {
        const int c = i >> 7, r = i & 127;
        const int pf = row0 + r;
        const int b  = pf / SP;
        const int p  = pf - b * SP;
        out[((size_t)b * CDIM + c0 + c) * SP + p] = sT[c * 132 + r] + sBias[c];
    }
}

// ---------------------------------------------------------------------------
extern "C" void kernel_launch(void* const* d_in, const int* in_sizes, int n_in,
                              void* d_out, int out_size)
{
    const float* x    = (const float*)d_in[0];
    const float* Wk   = (const float*)d_in[2];
    const float* Wv   = (const float*)d_in[3];
    const float* Wq   = (const float*)d_in[4];
    const float* Wout = (const float*)d_in[5];
    const float* bout = (const float*)d_in[6];
    float* out = (float*)d_out;

    cudaFuncSetAttribute(proj_mma_kernel, cudaFuncAttributeMaxDynamicSharedMemorySize,
                         PJ_SMEM);
    cudaFuncSetAttribute(attn_kernel, cudaFuncAttributeMaxDynamicSharedMemorySize,
                         ATTN_SMEM_BYTES);
    cudaFuncSetAttribute(outproj_mma_kernel, cudaFuncAttributeMaxDynamicSharedMemorySize,
                         OP_SMEM);

    convertX_kernel<<<dim3(SP / 64, CDIM / 64, BATCH), 256>>>(x);
    convertW_kernel<<<256, 256>>>(Wk, Wv, Wq, Wout);
    proj_mma_kernel<<<dim3(NPOS / 128, CDIM / 64), 256, PJ_SMEM>>>();
    attn_kernel<<<dim3(NWIN, 2), 128, ATTN_SMEM_BYTES>>>();
    outproj_mma_kernel<<<dim3(NPOS / 128, CDIM / 64), 256, OP_SMEM>>>(bout, out);
}

// round 12
// speedup vs baseline: 2.1714x; 1.0004x over previous
#include <cuda_runtime.h>
#include <cuda_bf16.h>
#include <stdint.h>

#define BATCH 4
#define CDIM  256
#define HH    120
#define WWID  120
#define SP    (HH*WWID)
#define NB    24
#define NWIN  (BATCH*NB*NB)       // 2304
#define NPOS  (BATCH*SP)          // 57600
#define QSCALE 0.17677669529663688f

#define NEGW  (-0.5f)
#define POSW  (4.0f/3.0f)
#define NORW  (-0.375f)
#define CNORW (4.0f)
#define PW    (1.8333333333333333f)   // POSW - NEGW
#define C0W   (4.375f)                // CNORW - NORW

// fp32 projections (read by attn)
__device__ float g_xk[NPOS*CDIM];
__device__ float g_xv[NPOS*CDIM];
__device__ float g_xq[NPOS*CDIM];
// bf16 split inputs for MMA
__device__ __nv_bfloat16 g_xh[NPOS*CDIM];
__device__ __nv_bfloat16 g_xl[NPOS*CDIM];
__device__ __nv_bfloat16 g_yh[NPOS*CDIM];
__device__ __nv_bfloat16 g_yl[NPOS*CDIM];
__device__ __nv_bfloat16 g_wh[4*CDIM*CDIM];   // Wk,Wv,Wq,Wout
__device__ __nv_bfloat16 g_wl[4*CDIM*CDIM];

__device__ __forceinline__ uint32_t sptr(const void* p) {
    return (uint32_t)__cvta_generic_to_shared(p);
}

#define LDM_X4(R, A) asm volatile( \
    "ldmatrix.sync.aligned.m8n8.x4.shared.b16 {%0,%1,%2,%3}, [%4];" \
    : "=r"((R)[0]), "=r"((R)[1]), "=r"((R)[2]), "=r"((R)[3]) : "r"(A))

#define MMA_BF16(D, A, B0, B1) asm volatile( \
    "mma.sync.aligned.m16n8k16.row.col.f32.bf16.bf16.f32 " \
    "{%0,%1,%2,%3},{%4,%5,%6,%7},{%8,%9},{%0,%1,%2,%3};" \
    : "+f"((D)[0]), "+f"((D)[1]), "+f"((D)[2]), "+f"((D)[3]) \
    : "r"((A)[0]), "r"((A)[1]), "r"((A)[2]), "r"((A)[3]), "r"(B0), "r"(B1))

#define CP_ASYNC16(dst, src) asm volatile( \
    "cp.async.cg.shared.global [%0], [%1], 16;" :: "r"(dst), "l"(src))
#define CP_COMMIT() asm volatile("cp.async.commit_group;")
#define CP_WAIT1()  asm volatile("cp.async.wait_group 1;")
#define CP_WAIT0()  asm volatile("cp.async.wait_group 0;")

// ---- packed f32x2 (Blackwell sm_100+) ----
#define FMA2(d, a, b) asm("fma.rn.f32x2 %0, %1, %2, %0;" : "+l"(d) : "l"(a), "l"(b))
#define ADD2(d, a, b) asm("add.rn.f32x2 %0, %1, %2;" : "=l"(d) : "l"(a), "l"(b))
#define PACK2(d, s)   asm("mov.b64 %0, {%1, %1};" : "=l"(d) : "r"(s))
#define UNPACK2(lo, hi, v) asm("mov.b64 {%0, %1}, %2;" : "=r"(lo), "=r"(hi) : "l"(v))

// ---------------------------------------------------------------------------
// Convert x [b][k][p] fp32 -> g_xh/g_xl [b*SP + p][k] bf16 hi/lo (transpose)
// ---------------------------------------------------------------------------
__global__ __launch_bounds__(256) void convertX_kernel(const float* __restrict__ x)
{
    __shared__ float st[64][65];
    const int p0 = blockIdx.x * 64;
    const int k0 = blockIdx.y * 64;
    const int b  = blockIdx.z;
    const int t  = threadIdx.x;

    for (int idx = t; idx < 4096; idx += 256) {
        const int k = idx >> 6, p = idx & 63;
        st[k][p] = x[((size_t)b * CDIM + k0 + k) * SP + p0 + p];
    }
    __syncthreads();
    for (int idx = t; idx < 2048; idx += 256) {
        const int p = idx >> 5, kk = idx & 31, k = kk * 2;
        const float v0 = st[k][p], v1 = st[k + 1][p];
        const __nv_bfloat16 h0 = __float2bfloat16(v0);
        const __nv_bfloat16 h1 = __float2bfloat16(v1);
        const __nv_bfloat16 l0 = __float2bfloat16(v0 - __bfloat162float(h0));
        const __nv_bfloat16 l1 = __float2bfloat16(v1 - __bfloat162float(h1));
        const size_t o = ((size_t)b * SP + p0 + p) * CDIM + k0 + k;
        *(__nv_bfloat162*)&g_xh[o] = __halves2bfloat162(h0, h1);
        *(__nv_bfloat162*)&g_xl[o] = __halves2bfloat162(l0, l1);
    }
}

__global__ __launch_bounds__(256) void convertW_kernel(
    const float* __restrict__ Wk, const float* __restrict__ Wv,
    const float* __restrict__ Wq, const float* __restrict__ Wout)
{
    const int i = blockIdx.x * 256 + threadIdx.x;   // 0..65535
    const float* srcs[4] = {Wk, Wv, Wq, Wout};
#pragma unroll
    for (int m = 0; m < 4; m++) {
        const float v = srcs[m][i];
        const __nv_bfloat16 h = __float2bfloat16(v);
        g_wh[m * 65536 + i] = h;
        g_wl[m * 65536 + i] = __float2bfloat16(v - __bfloat162float(h));
    }
}

// ---------------------------------------------------------------------------
// proj3 via mma.sync, cp.async double-buffered.  KC=32, 8 chunks.
// ---------------------------------------------------------------------------
#define PJ_STAGE 51200
#define PJ_SMEM  (2*PJ_STAGE)      // 102400

__device__ __forceinline__ void pj_load_chunk(char* base, int t, int row0, int c0,
                                              int chunk)
{
    const int kc = chunk * 32;
    for (int i = t; i < 1024; i += 256) {
        const int half = i >> 9, r = (i >> 2) & 127, seg = i & 3;
        const __nv_bfloat16* src = (half ? g_xl : g_xh)
            + (size_t)(row0 + r) * CDIM + kc + seg * 8;
        CP_ASYNC16(sptr(base + half * 10240 + r * 80 + seg * 16), src);
    }
    for (int i = t; i < 1536; i += 256) {
        const int half = (i >= 768), rem = i - half * 768;
        const int pr = rem >> 8, rr = (rem >> 2) & 63, seg = rem & 3;
        const __nv_bfloat16* src = (half ? g_wl : g_wh)
            + (size_t)pr * 65536 + (size_t)(c0 + rr) * CDIM + kc + seg * 8;
        CP_ASYNC16(sptr(base + 20480 + half * 15360 + pr * 5120 + rr * 80 + seg * 16),
                   src);
    }
}

__global__ __launch_bounds__(256, 2) void proj_mma_kernel()
{
    extern __shared__ char smem[];
    const int t = threadIdx.x;
    const int warp = t >> 5, lane = t & 31;
    const int wm = warp >> 1, wn = warp & 1;
    const int row0 = blockIdx.x * 128;
    const int c0   = blockIdx.y * 64;

    float acc[3][2][4][4];
#pragma unroll
    for (int a = 0; a < 3; a++)
#pragma unroll
        for (int b = 0; b < 2; b++)
#pragma unroll
            for (int c = 0; c < 4; c++)
#pragma unroll
                for (int d = 0; d < 4; d++) acc[a][b][c][d] = 0.f;

    pj_load_chunk(smem, t, row0, c0, 0);
    CP_COMMIT();

    for (int ch = 0; ch < 8; ch++) {
        if (ch < 7) {
            pj_load_chunk(smem + ((ch + 1) & 1) * PJ_STAGE, t, row0, c0, ch + 1);
            CP_COMMIT();
            CP_WAIT1();
        } else {
            CP_WAIT0();
        }
        __syncthreads();
        char* base = smem + (ch & 1) * PJ_STAGE;

#pragma unroll
        for (int ks = 0; ks < 2; ks++) {
            uint32_t Ah[2][4], Al[2][4];
            const int colb = ks * 32 + ((lane >> 4) << 4);
#pragma unroll
            for (int mt = 0; mt < 2; mt++) {
                const int r = wm * 32 + mt * 16 + (lane & 15);
                LDM_X4(Ah[mt], sptr(base + r * 80 + colb));
                LDM_X4(Al[mt], sptr(base + 10240 + r * 80 + colb));
            }
#pragma unroll
            for (int pr = 0; pr < 3; pr++) {
#pragma unroll
                for (int pair = 0; pair < 2; pair++) {
                    const int nr = wn * 32 + pair * 16 + (lane & 15);
                    uint32_t bh[4], bl[4];
                    LDM_X4(bh, sptr(base + 20480 + pr * 5120 + nr * 80 + colb));
                    LDM_X4(bl, sptr(base + 35840 + pr * 5120 + nr * 80 + colb));
#pragma unroll
                    for (int mt = 0; mt < 2; mt++) {
#pragma unroll
                        for (int sub = 0; sub < 2; sub++) {
                            const int nt = pair * 2 + sub;
                            MMA_BF16(acc[pr][mt][nt], Ah[mt], bh[sub], bh[sub + 2]);
                            MMA_BF16(acc[pr][mt][nt], Ah[mt], bl[sub], bl[sub + 2]);
                            MMA_BF16(acc[pr][mt][nt], Al[mt], bh[sub], bh[sub + 2]);
                        }
                    }
                }
            }
        }
        __syncthreads();
    }

    const int rbase = row0 + wm * 32 + (lane >> 2);
    const int cbase = c0 + wn * 32 + (lane & 3) * 2;
    float* dsts[3] = {g_xk, g_xv, g_xq};
#pragma unroll
    for (int pr = 0; pr < 3; pr++) {
        const float s = (pr == 2) ? QSCALE : 1.f;
#pragma unroll
        for (int mt = 0; mt < 2; mt++) {
#pragma unroll
            for (int nt = 0; nt < 4; nt++) {
                const int r = rbase + mt * 16;
                const int c = cbase + nt * 8;
                float* d = dsts[pr];
                *(float2*)&d[(size_t)r * CDIM + c] =
                    make_float2(acc[pr][mt][nt][0] * s, acc[pr][mt][nt][1] * s);
                *(float2*)&d[(size_t)(r + 8) * CDIM + c] =
                    make_float2(acc[pr][mt][nt][2] * s, acc[pr][mt][nt][3] * s);
            }
        }
    }
}

// ---------------------------------------------------------------------------
// attn: CTA = (window, head-half). 128 threads = 4 warps = 4 heads, lane = q.
// Phase 1: S[p] streamed to smem at strip_base + p*32 + lane — i.e. INTO row p
// of this warp's own (just-read) K strip.  Row p is fully consumed by the
// converged warp before the store instruction issues, and warp h touches only
// strip h -> race-free.  Store/load bank = lane -> conflict-free.
// Phase 2: rolling 3-column window reads S as Ss[i*32]; fused AV over sV.
// ---------------------------------------------------------------------------
#define ATTN_SMEM_BYTES (2 * 4 * 49 * 32 * 4)   // 50176
__global__ __launch_bounds__(128, 4) void attn_kernel()
{
    extern __shared__ float sm_att[];
    float* sK = sm_att;                // 6272 floats; overwritten row-by-row by S
    float* sV = sm_att + 4 * 49 * 32;

    const int blk  = blockIdx.x;
    const int half = blockIdx.y;
    const int b    = blk / (NB * NB);
    const int wrem = blk % (NB * NB);
    const int wy = wrem / NB, wx = wrem % NB;
    const int t = threadIdx.x;
    const int c0 = half * 128;

    const int ky0 = wy * 5 - 1, kx0 = wx * 5 - 1;
    for (int idx = t; idx < 49 * 32; idx += 128) {
        const int r  = idx >> 5;
        const int c4 = idx & 31;
        const int y  = ky0 + r / 7;
        const int xx = kx0 + r % 7;
        float4 vk = make_float4(0.f, 0.f, 0.f, 0.f);
        float4 vv = make_float4(0.f, 0.f, 0.f, 0.f);
        if (y >= 0 && y < HH && xx >= 0 && xx < WWID) {
            const size_t g = ((size_t)b * SP + y * WWID + xx) * CDIM + c0 + c4 * 4;
            vk = *(const float4*)&g_xk[g];
            vv = *(const float4*)&g_xv[g];
        }
        const int f = c4 * 4, hl = f >> 5, cc = f & 31;
        *(float4*)&sK[(hl * 49 + r) * 32 + cc] = vk;
        *(float4*)&sV[(hl * 49 + r) * 32 + cc] = vv;
    }
    __syncthreads();

    const int lane = t & 31;
    const int hl   = t >> 5;          // warp = head within this half
    if (lane < 25) {
        const int q = lane;
        const int qy = q / 5, qx = q % 5;
        const size_t qpos = ((size_t)b * SP + (wy * 5 + qy) * WWID + wx * 5 + qx) * CDIM
                            + (half * 4 + hl) * 32;
        // lane's S storage: strip_base + p*32 + lane  (inside row p, bank=lane)
        float* Ss = &sK[hl * 49 * 32 + lane];

        float m;
        {
            // Q as 16 packed f32x2
            unsigned long long qp[16];
#pragma unroll
            for (int j = 0; j < 8; j++) {
                const ulonglong2 v = *(const ulonglong2*)&g_xq[qpos + j * 4];
                qp[2*j] = v.x; qp[2*j+1] = v.y;
            }

            // S[p] = Q . K_p, stored into row p right after the warp reads it.
            float mpos = -3.4e38f, mneg = 3.4e38f;
#pragma unroll
            for (int p = 0; p < 49; p++) {
                const float* kr = &sK[(hl * 49 + p) * 32];
                unsigned long long a0 = 0ull, a1 = 0ull;
#pragma unroll
                for (int j = 0; j < 8; j++) {
                    const ulonglong2 kv = *(const ulonglong2*)&kr[j * 4];
                    FMA2(a0, qp[2*j],   kv.x);
                    FMA2(a1, qp[2*j+1], kv.y);
                }
                unsigned long long asum; ADD2(asum, a0, a1);
                uint32_t lo, hi; UNPACK2(lo, hi, asum);
                const float sv = __uint_as_float(lo) + __uint_as_float(hi);
                mpos = fmaxf(mpos, sv);
                mneg = fminf(mneg, sv);
                Ss[p * 32] = sv;
            }
            m = 4.0f * mpos - 3.0f * mneg;
        }

        // phase 2: streaming 3-row A window + fused AV
        unsigned long long o2[16];
#pragma unroll
        for (int j = 0; j < 16; j++) o2[j] = 0ull;
        float A0[7], A1[7], A2[7];
#pragma unroll
        for (int j = 0; j < 7; j++) { A0[j] = 0.f; A1[j] = 0.f; A2[j] = 0.f; }

        float ssum = 0.f;
#pragma unroll
        for (int ky = 0; ky < 5; ky++) {
            // rolling 3x3 column window over S rows ky..ky+2
            float a0 = Ss[(ky*7)*32],       a1 = Ss[((ky+1)*7)*32],       a2 = Ss[((ky+2)*7)*32];
            float b0 = Ss[(ky*7 + 1)*32],   b1 = Ss[((ky+1)*7 + 1)*32],   b2 = Ss[((ky+2)*7 + 1)*32];
#pragma unroll
            for (int kx = 0; kx < 5; kx++) {
                const float t0 = Ss[(ky*7 + kx + 2)*32];
                const float t1 = Ss[((ky+1)*7 + kx + 2)*32];
                const float t2 = Ss[((ky+2)*7 + kx + 2)*32];
                const float tl = a0, l = a1, bl = a2;
                const float u  = b0, c = b1, d  = b2;
                const float tr = t0, r = t1, br = t2;
                const float s_ud = u + d, s_lr = l + r;
                const float dg = tl + br, ad = tr + bl;
                const float sum9 = ((s_ud + s_lr) + (dg + ad)) + c;
                const float base = fmaf(NEGW, sum9, -m);
                const float e0 = __expf(fmaf(NORW, sum9, fmaf(C0W, c, -m)));
                const float e1 = __expf(fmaf(PW, s_ud + c, base));
                const float e2 = __expf(fmaf(PW, s_lr + c, base));
                const float e3 = __expf(fmaf(PW, dg + c, base));
                const float e4 = __expf(fmaf(PW, ad + c, base));
                const float e5 = __expf(fmaf(PW, (u + l) + c, base));
                const float e6 = __expf(fmaf(PW, (u + r) + c, base));
                const float e7 = __expf(fmaf(PW, (l + d) + c, base));
                const float e8 = __expf(fmaf(PW, (r + d) + c, base));
                const float E = ((e1 + e2) + (e3 + e4)) + ((e5 + e6) + (e7 + e8));
                ssum += E + e0;
                const float basea = fmaf(NEGW, E, NORW * e0);
                A0[kx  ] += fmaf(PW, e3, basea);
                A0[kx+1] += fmaf(PW, (e1 + e5) + e6, basea);
                A0[kx+2] += fmaf(PW, e4, basea);
                A1[kx  ] += fmaf(PW, (e2 + e5) + e7, basea);
                A1[kx+1] += fmaf(PW, E, fmaf(C0W, e0, basea));
                A1[kx+2] += fmaf(PW, (e2 + e6) + e8, basea);
                A2[kx  ] += fmaf(PW, e4, basea);
                A2[kx+1] += fmaf(PW, (e1 + e7) + e8, basea);
                A2[kx+2] += fmaf(PW, e3, basea);
                a0 = b0; a1 = b1; a2 = b2;
                b0 = t0; b1 = t1; b2 = t2;
            }
            // row ky is final: fused AV (V loads broadcast warp-wide)
#pragma unroll
            for (int px = 0; px < 7; px++) {
                unsigned long long aa; PACK2(aa, __float_as_uint(A0[px]));
                const float* vr = &sV[(hl * 49 + ky * 7 + px) * 32];
#pragma unroll
                for (int j = 0; j < 8; j++) {
                    const ulonglong2 vv = *(const ulonglong2*)&vr[j * 4];
                    FMA2(o2[2*j],   aa, vv.x);
                    FMA2(o2[2*j+1], aa, vv.y);
                }
            }
#pragma unroll
            for (int j = 0; j < 7; j++) { A0[j] = A1[j]; A1[j] = A2[j]; A2[j] = 0.f; }
        }
        // rows 5 (A0) and 6 (A1)
#pragma unroll
        for (int rr = 0; rr < 2; rr++) {
#pragma unroll
            for (int px = 0; px < 7; px++) {
                const float a = rr ? A1[px] : A0[px];
                unsigned long long aa; PACK2(aa, __float_as_uint(a));
                const float* vr = &sV[(hl * 49 + (5 + rr) * 7 + px) * 32];
#pragma unroll
                for (int j = 0; j < 8; j++) {
                    const ulonglong2 vv = *(const ulonglong2*)&vr[j * 4];
                    FMA2(o2[2*j],   aa, vv.x);
                    FMA2(o2[2*j+1], aa, vv.y);
                }
            }
        }

        const float inv = 1.0f / ssum;
        uint32_t hw[16], lw[16];
#pragma unroll
        for (int j = 0; j < 16; j++) {
            uint32_t lo, hi; UNPACK2(lo, hi, o2[j]);
            const float v0 = __uint_as_float(lo) * inv;
            const float v1 = __uint_as_float(hi) * inv;
            const __nv_bfloat16 h0 = __float2bfloat16(v0);
            const __nv_bfloat16 h1 = __float2bfloat16(v1);
            const __nv_bfloat16 l0 = __float2bfloat16(v0 - __bfloat162float(h0));
            const __nv_bfloat16 l1 = __float2bfloat16(v1 - __bfloat162float(h1));
            __nv_bfloat162 hp = __halves2bfloat162(h0, h1);
            __nv_bfloat162 lp = __halves2bfloat162(l0, l1);
            hw[j] = *(uint32_t*)&hp;
            lw[j] = *(uint32_t*)&lp;
        }
#pragma unroll
        for (int j = 0; j < 4; j++) {
            *(uint4*)&g_yh[qpos + j * 8] = make_uint4(hw[4*j], hw[4*j+1], hw[4*j+2], hw[4*j+3]);
            *(uint4*)&g_yl[qpos + j * 8] = make_uint4(lw[4*j], lw[4*j+1], lw[4*j+2], lw[4*j+3]);
        }
    }
}

// ---------------------------------------------------------------------------
// outproj via mma.sync, cp.async double-buffered.  KC=32, 8 chunks.
// ---------------------------------------------------------------------------
#define OP_STAGE 30720
#define OP_BIAS  (2*OP_STAGE)              // 61440, 256B bias
#define OP_SMEM  (2*OP_STAGE + 256)

__device__ __forceinline__ void op_load_chunk(char* base, int t, int row0, int c0,
                                              int chunk)
{
    const int kc = chunk * 32;
    for (int i = t; i < 1024; i += 256) {
        const int half = i >> 9, r = (i >> 2) & 127, seg = i & 3;
        const __nv_bfloat16* src = (half ? g_yl : g_yh)
            + (size_t)(row0 + r) * CDIM + kc + seg * 8;
        CP_ASYNC16(sptr(base + half * 10240 + r * 80 + seg * 16), src);
    }
    for (int i = t; i < 512; i += 256) {
        const int half = i >> 8, rr = (i >> 2) & 63, seg = i & 3;
        const __nv_bfloat16* src = (half ? g_wl : g_wh)
            + (size_t)3 * 65536 + (size_t)(c0 + rr) * CDIM + kc + seg * 8;
        CP_ASYNC16(sptr(base + 20480 + half * 5120 + rr * 80 + seg * 16), src);
    }
}

__global__ __launch_bounds__(256, 2) void outproj_mma_kernel(
    const float* __restrict__ bout, float* __restrict__ out)
{
    extern __shared__ char smem[];
    float* sT = (float*)smem;
    float* sBias = (float*)(smem + OP_BIAS);
    const int t = threadIdx.x;
    const int warp = t >> 5, lane = t & 31;
    const int wm = warp >> 1, wn = warp & 1;
    const int row0 = blockIdx.x * 128;
    const int c0   = blockIdx.y * 64;

    if (t < 64) sBias[t] = bout[c0 + t];

    float acc[2][4][4];
#pragma unroll
    for (int b = 0; b < 2; b++)
#pragma unroll
        for (int c = 0; c < 4; c++)
#pragma unroll
            for (int d = 0; d < 4; d++) acc[b][c][d] = 0.f;

    op_load_chunk(smem, t, row0, c0, 0);
    CP_COMMIT();

    for (int ch = 0; ch < 8; ch++) {
        if (ch < 7) {
            op_load_chunk(smem + ((ch + 1) & 1) * OP_STAGE, t, row0, c0, ch + 1);
            CP_COMMIT();
            CP_WAIT1();
        } else {
            CP_WAIT0();
        }
        __syncthreads();
        char* base = smem + (ch & 1) * OP_STAGE;

#pragma unroll
        for (int ks = 0; ks < 2; ks++) {
            uint32_t Ah[2][4], Al[2][4];
            const int colb = ks * 32 + ((lane >> 4) << 4);
#pragma unroll
            for (int mt = 0; mt < 2; mt++) {
                const int r = wm * 32 + mt * 16 + (lane & 15);
                LDM_X4(Ah[mt], sptr(base + r * 80 + colb));
                LDM_X4(Al[mt], sptr(base + 10240 + r * 80 + colb));
            }
#pragma unroll
            for (int pair = 0; pair < 2; pair++) {
                const int nr = wn * 32 + pair * 16 + (lane & 15);
                uint32_t bh[4], bl[4];
                LDM_X4(bh, sptr(base + 20480 + nr * 80 + colb));
                LDM_X4(bl, sptr(base + 25600 + nr * 80 + colb));
#pragma unroll
                for (int mt = 0; mt < 2; mt++) {
#pragma unroll
                    for (int sub = 0; sub < 2; sub++) {
                        const int nt = pair * 2 + sub;
                        MMA_BF16(acc[mt][nt], Ah[mt], bh[sub], bh[sub + 2]);
                        MMA_BF16(acc[mt][nt], Ah[mt], bl[sub], bl[sub + 2]);
                        MMA_BF16(acc[mt][nt], Al[mt], bh[sub], bh[sub + 2]);
                    }
                }
            }
        }
        __syncthreads();
    }

    const int rl = wm * 32 + (lane >> 2);
    const int cl = wn * 32 + (lane & 3) * 2;
#pragma unroll
    for (int mt = 0; mt < 2; mt++) {
#pragma unroll
        for (int nt = 0; nt < 4; nt++) {
            const int r = rl + mt * 16;
            const int c = cl + nt * 8;
            sT[(c    ) * 132 + r    ] = acc[mt][nt][0];
            sT[(c + 1) * 132 + r    ] = acc[mt][nt][1];
            sT[(c    ) * 132 + r + 8] = acc[mt][nt][2];
            sT[(c + 1) * 132 + r + 8] = acc[mt][nt][3];
        }
    }
    __syncthreads();

    for (int i = t; i < 8192; i += 256) {
        const int c = i >> 7, r = i & 127;
        const int pf = row0 + r;
        const int b  = pf / SP;
        const int p  = pf - b * SP;
        out[((size_t)b * CDIM + c0 + c) * SP + p] = sT[c * 132 + r] + sBias[c];
    }
}

// ---------------------------------------------------------------------------
extern "C" void kernel_launch(void* const* d_in, const int* in_sizes, int n_in,
                              void* d_out, int out_size)
{
    const float* x    = (const float*)d_in[0];
    const float* Wk   = (const float*)d_in[2];
    const float* Wv   = (const float*)d_in[3];
    const float* Wq   = (const float*)d_in[4];
    const float* Wout = (const float*)d_in[5];
    const float* bout = (const float*)d_in[6];
    float* out = (float*)d_out;

    cudaFuncSetAttribute(proj_mma_kernel, cudaFuncAttributeMaxDynamicSharedMemorySize,
                         PJ_SMEM);
    cudaFuncSetAttribute(attn_kernel, cudaFuncAttributeMaxDynamicSharedMemorySize,
                         ATTN_SMEM_BYTES);
    cudaFuncSetAttribute(outproj_mma_kernel, cudaFuncAttributeMaxDynamicSharedMemorySize,
                         OP_SMEM);

    convertX_kernel<<<dim3(SP / 64, CDIM / 64, BATCH), 256>>>(x);
    convertW_kernel<<<256, 256>>>(Wk, Wv, Wq, Wout);
    proj_mma_kernel<<<dim3(NPOS / 128, CDIM / 64), 256, PJ_SMEM>>>();
    attn_kernel<<<dim3(NWIN, 2), 128, ATTN_SMEM_BYTES>>>();
    outproj_mma_kernel<<<dim3(NPOS / 128, CDIM / 64), 256, OP_SMEM>>>(bout, out);
}